// round 3
// baseline (speedup 1.0000x reference)
#include <cuda_runtime.h>
#include <cuda_bf16.h>
#include <math.h>

#define NSEQ 1024
#define CS   384
#define CZ   128
#define NH   16
#define DH   24
#define HC   384
#define NN   (NSEQ*NSEQ)
#define RSQRT_D 0.2041241452319315f

typedef unsigned long long u64;

__device__ __forceinline__ u64 pk2(float a, float b) {
    u64 r; asm("mov.b64 %0,{%1,%2};" : "=l"(r) : "f"(a), "f"(b)); return r;
}
__device__ __forceinline__ void upk2(u64 v, float& a, float& b) {
    asm("mov.b64 {%0,%1},%2;" : "=f"(a), "=f"(b) : "l"(v));
}
__device__ __forceinline__ u64 ffma2(u64 a, u64 b, u64 c) {
    u64 d; asm("fma.rn.f32x2 %0,%1,%2,%3;" : "=l"(d) : "l"(a), "l"(b), "l"(c)); return d;
}
__device__ __forceinline__ u64 fadd2(u64 a, u64 b) {
    u64 d; asm("add.rn.f32x2 %0,%1,%2;" : "=l"(d) : "l"(a), "l"(b)); return d;
}
__device__ __forceinline__ float sigm(float x) { return 1.0f / (1.0f + __expf(-x)); }

// ------------- scratch (static device globals; no allocs allowed) -------------
__device__ float g_aln[NSEQ * CS];
__device__ float g_sln[NSEQ * CS];
__device__ float g_a  [NSEQ * CS];
__device__ float g_q  [NH * NSEQ * DH];   // [h][i][d], pre-scaled by 1/sqrt(D)
__device__ float g_k  [NH * NSEQ * DH];
__device__ float g_v  [NH * NSEQ * DH];
__device__ float g_g  [NH * NSEQ * DH];
__device__ float g_bias[(size_t)NH * NN]; // [h][i][j], 64 MB
__device__ float g_o  [NSEQ * HC];        // gated attention output [i][h*D+d]

// =====================================================================
// Kernel 0: row layer norms of a_i and s_i.  grid 1024, block 384.
// =====================================================================
__global__ void __launch_bounds__(384) k_ln(const float* __restrict__ a_i,
                                            const float* __restrict__ s_i,
                                            const float* __restrict__ lnw) {
    __shared__ float red[12][4];
    __shared__ float bcv[4];
    int i = blockIdx.x, t = threadIdx.x;
    float av = a_i[i * CS + t];
    float sv = s_i[i * CS + t];
    float r0 = av, r1 = av * av, r2 = sv, r3 = sv * sv;
    #pragma unroll
    for (int o = 16; o > 0; o >>= 1) {
        r0 += __shfl_down_sync(0xffffffffu, r0, o);
        r1 += __shfl_down_sync(0xffffffffu, r1, o);
        r2 += __shfl_down_sync(0xffffffffu, r2, o);
        r3 += __shfl_down_sync(0xffffffffu, r3, o);
    }
    if ((t & 31) == 0) { int w = t >> 5; red[w][0]=r0; red[w][1]=r1; red[w][2]=r2; red[w][3]=r3; }
    __syncthreads();
    if (t == 0) {
        float s0=0, s1=0, s2=0, s3=0;
        #pragma unroll
        for (int w = 0; w < 12; w++) { s0+=red[w][0]; s1+=red[w][1]; s2+=red[w][2]; s3+=red[w][3]; }
        float ma = s0 * (1.0f/CS), ms = s2 * (1.0f/CS);
        float va = s1 * (1.0f/CS) - ma*ma;
        float vs = s3 * (1.0f/CS) - ms*ms;
        bcv[0]=ma; bcv[1]=rsqrtf(va + 1e-5f);
        bcv[2]=ms; bcv[3]=rsqrtf(vs + 1e-5f);
    }
    __syncthreads();
    g_aln[i*CS + t] = (av - bcv[0]) * bcv[1];
    g_sln[i*CS + t] = (sv - bcv[2]) * bcv[3] * lnw[t];
}

// =====================================================================
// Kernel 1: AdaLN:  a = sigmoid(sln@ws + bs)*aln + sln@wns
// grid (3,64), block 128; tile = 16 rows x 128 cols.
// =====================================================================
__global__ void __launch_bounds__(128) k_adaln(const float* __restrict__ ws,
                                               const float* __restrict__ bs,
                                               const float* __restrict__ wns) {
    __shared__ __align__(16) float st[CS * 18];   // transposed sln tile
    int i0 = blockIdx.y * 16;
    int t  = threadIdx.x;
    int c  = blockIdx.x * 128 + t;
    for (int r = 0; r < 16; r++)
        for (int kk = t; kk < CS; kk += 128)
            st[kk * 18 + r] = g_sln[(i0 + r) * CS + kk];
    __syncthreads();
    u64 a1[8], a2[8];
    #pragma unroll
    for (int p = 0; p < 8; p++) { a1[p] = 0ull; a2[p] = 0ull; }
    #pragma unroll 4
    for (int k = 0; k < CS; k++) {
        float w1 = ws[k * CS + c];
        float w2 = wns[k * CS + c];
        u64 w1p = pk2(w1, w1), w2p = pk2(w2, w2);
        const u64* sp = (const u64*)&st[k * 18];
        #pragma unroll
        for (int p = 0; p < 8; p++) {
            u64 sv = sp[p];
            a1[p] = ffma2(sv, w1p, a1[p]);
            a2[p] = ffma2(sv, w2p, a2[p]);
        }
    }
    float bsc = bs[c];
    #pragma unroll
    for (int p = 0; p < 8; p++) {
        float x0, x1, y0, y1;
        upk2(a1[p], x0, x1); upk2(a2[p], y0, y1);
        int r0 = i0 + 2 * p;
        g_a[r0 * CS + c]       = sigm(x0 + bsc) * g_aln[r0 * CS + c]       + y0;
        g_a[(r0 + 1) * CS + c] = sigm(x1 + bsc) * g_aln[(r0 + 1) * CS + c] + y1;
    }
}

// =====================================================================
// Kernel 2: QKV + gate projections.  grid (3,64,4), block 128.
// =====================================================================
__global__ void __launch_bounds__(128) k_qkvg(const float* __restrict__ wq,
                                              const float* __restrict__ bq,
                                              const float* __restrict__ wk,
                                              const float* __restrict__ wv,
                                              const float* __restrict__ wg) {
    __shared__ __align__(16) float at[CS * 18];
    int m  = blockIdx.z;
    int i0 = blockIdx.y * 16;
    int t  = threadIdx.x;
    int c  = blockIdx.x * 128 + t;
    for (int r = 0; r < 16; r++)
        for (int kk = t; kk < CS; kk += 128)
            at[kk * 18 + r] = g_a[(i0 + r) * CS + kk];
    __syncthreads();
    const float* w = (m == 0) ? wq : (m == 1) ? wk : (m == 2) ? wv : wg;
    u64 acc[8];
    #pragma unroll
    for (int p = 0; p < 8; p++) acc[p] = 0ull;
    #pragma unroll 4
    for (int k = 0; k < CS; k++) {
        float wv_ = w[k * CS + c];
        u64 wp = pk2(wv_, wv_);
        const u64* ap = (const u64*)&at[k * 18];
        #pragma unroll
        for (int p = 0; p < 8; p++) acc[p] = ffma2(ap[p], wp, acc[p]);
    }
    int h = c / DH, d = c - h * DH;
    float bqc = (m == 0) ? bq[c] : 0.0f;
    #pragma unroll
    for (int p = 0; p < 8; p++) {
        float v0, v1; upk2(acc[p], v0, v1);
        int r0 = i0 + 2 * p;
        int idx0 = h * (NSEQ * DH) + r0 * DH + d;
        int idx1 = idx0 + DH;
        if (m == 0)      { g_q[idx0] = (v0 + bqc) * RSQRT_D; g_q[idx1] = (v1 + bqc) * RSQRT_D; }
        else if (m == 1) { g_k[idx0] = v0;                   g_k[idx1] = v1; }
        else if (m == 2) { g_v[idx0] = v0;                   g_v[idx1] = v1; }
        else             { g_g[idx0] = sigm(v0);             g_g[idx1] = sigm(v1); }
    }
}

// =====================================================================
// Kernel 3: pair bias.  bias[h,i,j] = rstd*(S_h - mean*W_h) + C_h
//   S_h = sum_c z[i,j,c]*(lnw_c*wb[c,h]),  mean/rstd from raw z.
// grid (8 jTiles, 1024 i), block 128, dyn smem ~74 KB. Thread = one pair.
// =====================================================================
#define PAIR_SMEM (128*132*4 + NH*64*8 + 2*NH*4)
__global__ void __launch_bounds__(128) k_pair(const float* __restrict__ z,
                                              const float* __restrict__ lnw,
                                              const float* __restrict__ lnb,
                                              const float* __restrict__ wb) {
    extern __shared__ float sm[];
    float* zs  = sm;                             // 128 rows x 132 floats (padded)
    u64*   wsm = (u64*)(sm + 128 * 132);         // [h][64] packed c-pairs
    float* WH  = (float*)(wsm + NH * 64);
    float* CH  = WH + NH;
    int t  = threadIdx.x;
    int i  = blockIdx.y;
    int j0 = blockIdx.x * 128;

    for (int idx = t; idx < NH * 64; idx += 128) {
        int h = idx >> 6, c2 = idx & 63;
        wsm[idx] = pk2(lnw[2*c2]     * wb[(2*c2)     * NH + h],
                       lnw[2*c2 + 1] * wb[(2*c2 + 1) * NH + h]);
    }
    if (t < NH) {
        float W = 0, C = 0;
        for (int cc = 0; cc < CZ; cc++) {
            float wv = wb[cc * NH + t];
            W += lnw[cc] * wv; C += lnb[cc] * wv;
        }
        WH[t] = W; CH[t] = C;
    }
    const float4* zg = (const float4*)(z + (size_t)i * (NSEQ * CZ) + (size_t)j0 * CZ);
    for (int f = t; f < 128 * 32; f += 128) {
        int jl = f >> 5, c4 = f & 31;
        *(float4*)&zs[jl * 132 + c4 * 4] = zg[(size_t)jl * 32 + c4];
    }
    __syncthreads();

    u64 acc[NH];
    #pragma unroll
    for (int h = 0; h < NH; h++) acc[h] = 0ull;
    u64 s2 = 0ull, q2 = 0ull;
    const float* zr = zs + t * 132;
    #pragma unroll 2
    for (int c4 = 0; c4 < 32; c4++) {
        float4 v = *(const float4*)&zr[c4 * 4];
        u64 v01 = pk2(v.x, v.y), v23 = pk2(v.z, v.w);
        s2 = fadd2(s2, fadd2(v01, v23));
        q2 = ffma2(v01, v01, q2);
        q2 = ffma2(v23, v23, q2);
        const u64* base = wsm + 2 * c4;
        #pragma unroll
        for (int h = 0; h < NH; h++) {
            ulonglong2 wv2 = *(const ulonglong2*)(base + h * 64);   // broadcast
            acc[h] = ffma2(v01, wv2.x, acc[h]);
            acc[h] = ffma2(v23, wv2.y, acc[h]);
        }
    }
    float sa, sb, qa, qb;
    upk2(s2, sa, sb); upk2(q2, qa, qb);
    float mean = (sa + sb) * (1.0f / CZ);
    float var  = (qa + qb) * (1.0f / CZ) - mean * mean;
    float rstd = rsqrtf(var + 1e-5f);
    int j = j0 + t;
    float* bo = g_bias + (size_t)i * NSEQ + j;
    #pragma unroll
    for (int h = 0; h < NH; h++) {
        float x0, x1; upk2(acc[h], x0, x1);
        bo[(size_t)h * NN] = ((x0 + x1) - mean * WH[h]) * rstd + CH[h];
    }
}

// =====================================================================
// Kernel 4: flash attention.  grid (64 iTiles, 16 heads), block 512.
// K,V for whole head staged in 200KB smem (stride 25 -> conflict-free).
// One warp per query row, online softmax, gate applied in epilogue.
// =====================================================================
#define ATT_SMEM (2 * NSEQ * 25 * 4)
__global__ void __launch_bounds__(512) k_attn() {
    extern __shared__ float sm[];
    float* ks_ = sm;
    float* vs_ = sm + NSEQ * 25;
    int h  = blockIdx.y;
    int i0 = blockIdx.x * 16;
    int t  = threadIdx.x;
    const float* kg = g_k + (size_t)h * NSEQ * DH;
    const float* vg = g_v + (size_t)h * NSEQ * DH;
    for (int e = t; e < NSEQ * DH; e += 512) {
        int j = e / DH, d = e - j * DH;
        ks_[j * 25 + d] = kg[e];
        vs_[j * 25 + d] = vg[e];
    }
    __syncthreads();
    int w = t >> 5, lane = t & 31;
    int i = i0 + w;
    float qv[DH];
    const float* qg = g_q + ((size_t)h * NSEQ + i) * DH;
    #pragma unroll
    for (int d = 0; d < DH; d++) qv[d] = qg[d];
    const float* bp = g_bias + (size_t)h * NN + (size_t)i * NSEQ;
    float m = -1e30f, l = 0.0f, o[DH];
    #pragma unroll
    for (int d = 0; d < DH; d++) o[d] = 0.0f;
    for (int s = 0; s < NSEQ / 32; s++) {
        int j = s * 32 + lane;
        const float* kr = ks_ + j * 25;
        float lg = bp[j];
        #pragma unroll
        for (int d = 0; d < DH; d++) lg += qv[d] * kr[d];
        float mx = lg;
        #pragma unroll
        for (int off = 16; off > 0; off >>= 1)
            mx = fmaxf(mx, __shfl_xor_sync(0xffffffffu, mx, off));
        if (mx > m) {                       // warp-uniform branch
            float corr = __expf(m - mx);
            l *= corr;
            #pragma unroll
            for (int d = 0; d < DH; d++) o[d] *= corr;
            m = mx;
        }
        float p = __expf(lg - m);
        l += p;
        const float* vr = vs_ + j * 25;
        #pragma unroll
        for (int d = 0; d < DH; d++) o[d] += p * vr[d];
    }
    #pragma unroll
    for (int off = 16; off > 0; off >>= 1) l += __shfl_xor_sync(0xffffffffu, l, off);
    #pragma unroll
    for (int d = 0; d < DH; d++) {
        #pragma unroll
        for (int off = 16; off > 0; off >>= 1)
            o[d] += __shfl_xor_sync(0xffffffffu, o[d], off);
    }
    if (lane == 0) {
        float inv = 1.0f / l;
        const float* gg = g_g + ((size_t)h * NSEQ + i) * DH;
        float* op = g_o + (size_t)i * HC + h * DH;
        #pragma unroll
        for (int d = 0; d < DH; d++) op[d] = o[d] * inv * gg[d];
    }
}

// =====================================================================
// Kernel 5: out = sigmoid(s_i@ws + bs) * (o@wo).  grid (3,64), block 128.
// =====================================================================
__global__ void __launch_bounds__(128) k_out(const float* __restrict__ s_i,
                                             const float* __restrict__ ws2,
                                             const float* __restrict__ bs2,
                                             const float* __restrict__ wo,
                                             float* __restrict__ out) {
    __shared__ __align__(16) float st[CS * 18];
    __shared__ __align__(16) float ot[CS * 18];
    int i0 = blockIdx.y * 16;
    int t  = threadIdx.x;
    int c  = blockIdx.x * 128 + t;
    for (int r = 0; r < 16; r++)
        for (int kk = t; kk < CS; kk += 128) {
            st[kk * 18 + r] = s_i[(i0 + r) * CS + kk];
            ot[kk * 18 + r] = g_o[(i0 + r) * CS + kk];
        }
    __syncthreads();
    u64 a1[8], a2[8];
    #pragma unroll
    for (int p = 0; p < 8; p++) { a1[p] = 0ull; a2[p] = 0ull; }
    #pragma unroll 4
    for (int k = 0; k < CS; k++) {
        float w1 = ws2[k * CS + c];
        float w2 = wo[k * CS + c];
        u64 w1p = pk2(w1, w1), w2p = pk2(w2, w2);
        const u64* sp = (const u64*)&st[k * 18];
        const u64* op = (const u64*)&ot[k * 18];
        #pragma unroll
        for (int p = 0; p < 8; p++) {
            a1[p] = ffma2(sp[p], w1p, a1[p]);
            a2[p] = ffma2(op[p], w2p, a2[p]);
        }
    }
    float bsc = bs2[c];
    #pragma unroll
    for (int p = 0; p < 8; p++) {
        float x0, x1, y0, y1;
        upk2(a1[p], x0, x1); upk2(a2[p], y0, y1);
        int r0 = i0 + 2 * p;
        out[r0 * CS + c]       = sigm(x0 + bsc) * y0;
        out[(r0 + 1) * CS + c] = sigm(x1 + bsc) * y1;
    }
}

// =====================================================================
extern "C" void kernel_launch(void* const* d_in, const int* in_sizes, int n_in,
                              void* d_out, int out_size) {
    const float* a_i   = (const float*)d_in[0];
    const float* s_i   = (const float*)d_in[1];
    const float* z     = (const float*)d_in[2];
    const float* lns_w = (const float*)d_in[3];
    const float* aws   = (const float*)d_in[4];
    const float* abs_  = (const float*)d_in[5];
    const float* awns  = (const float*)d_in[6];
    const float* wq    = (const float*)d_in[7];
    const float* bq    = (const float*)d_in[8];
    const float* wk    = (const float*)d_in[9];
    const float* wv    = (const float*)d_in[10];
    const float* lnb_w = (const float*)d_in[11];
    const float* lnb_b = (const float*)d_in[12];
    const float* wb    = (const float*)d_in[13];
    const float* wg    = (const float*)d_in[14];
    const float* wo    = (const float*)d_in[15];
    const float* ws2   = (const float*)d_in[16];
    const float* bs2   = (const float*)d_in[17];
    float* out = (float*)d_out;

    cudaFuncSetAttribute(k_pair, cudaFuncAttributeMaxDynamicSharedMemorySize, PAIR_SMEM);
    cudaFuncSetAttribute(k_attn, cudaFuncAttributeMaxDynamicSharedMemorySize, ATT_SMEM);

    k_ln<<<NSEQ, CS>>>(a_i, s_i, lns_w);
    k_pair<<<dim3(8, NSEQ), 128, PAIR_SMEM>>>(z, lnb_w, lnb_b, wb);
    k_adaln<<<dim3(3, 64), 128>>>(aws, abs_, awns);
    k_qkvg<<<dim3(3, 64, 4), 128>>>(wq, bq, wk, wv, wg);
    k_attn<<<dim3(64, 16), 512, ATT_SMEM>>>();
    k_out<<<dim3(3, 64), 128>>>(s_i, ws2, bs2, wo, out);
}

// round 4
// speedup vs baseline: 1.3570x; 1.3570x over previous
#include <cuda_runtime.h>
#include <cuda_bf16.h>
#include <math.h>

#define NSEQ 1024
#define CS   384
#define CZ   128
#define NH   16
#define DH   24
#define HC   384
#define NN   (NSEQ*NSEQ)
#define RSQRT_D 0.2041241452319315f

typedef unsigned long long u64;

__device__ __forceinline__ u64 pk2(float a, float b) {
    u64 r; asm("mov.b64 %0,{%1,%2};" : "=l"(r) : "f"(a), "f"(b)); return r;
}
__device__ __forceinline__ void upk2(u64 v, float& a, float& b) {
    asm("mov.b64 {%0,%1},%2;" : "=f"(a), "=f"(b) : "l"(v));
}
__device__ __forceinline__ u64 ffma2(u64 a, u64 b, u64 c) {
    u64 d; asm("fma.rn.f32x2 %0,%1,%2,%3;" : "=l"(d) : "l"(a), "l"(b), "l"(c)); return d;
}
__device__ __forceinline__ u64 fadd2(u64 a, u64 b) {
    u64 d; asm("add.rn.f32x2 %0,%1,%2;" : "=l"(d) : "l"(a), "l"(b)); return d;
}
__device__ __forceinline__ float sigm(float x) { return 1.0f / (1.0f + __expf(-x)); }

// ------------- scratch (static device globals) -------------
__device__ float g_aln[NSEQ * CS];
__device__ float g_sln[NSEQ * CS];
__device__ float g_a  [NSEQ * CS];
__device__ float g_q  [NH * NSEQ * DH];
__device__ float g_k  [NH * NSEQ * DH];
__device__ float g_v  [NH * NSEQ * DH];
__device__ float g_g  [NH * NSEQ * DH];
__device__ float g_bias[(size_t)NH * NN];   // [h][i][j], 64 MB
__device__ float g_o  [NSEQ * HC];
__device__ u64   g_wpk[NH * 64];            // packed lnw*wb pairs, [h][c2]
__device__ float g_WH[NH];
__device__ float g_CH[NH];

// =====================================================================
// Kernel P: one-time prep of pair-bias weights (hoisted out of k_pair).
// =====================================================================
__global__ void __launch_bounds__(128) k_prep(const float* __restrict__ lnw,
                                              const float* __restrict__ lnb,
                                              const float* __restrict__ wb) {
    int t = threadIdx.x;
    for (int idx = t; idx < NH * 64; idx += 128) {
        int h = idx >> 6, c2 = idx & 63;
        g_wpk[idx] = pk2(lnw[2*c2]     * wb[(2*c2)     * NH + h],
                         lnw[2*c2 + 1] * wb[(2*c2 + 1) * NH + h]);
    }
    if (t < NH) {
        float W = 0, C = 0;
        #pragma unroll 4
        for (int cc = 0; cc < CZ; cc++) {
            float wv = wb[cc * NH + t];
            W += lnw[cc] * wv; C += lnb[cc] * wv;
        }
        g_WH[t] = W; g_CH[t] = C;
    }
}

// =====================================================================
// Kernel 0: row layer norms of a_i and s_i.  grid 1024, block 384.
// =====================================================================
__global__ void __launch_bounds__(384) k_ln(const float* __restrict__ a_i,
                                            const float* __restrict__ s_i,
                                            const float* __restrict__ lnw) {
    __shared__ float red[12][4];
    __shared__ float bcv[4];
    int i = blockIdx.x, t = threadIdx.x;
    float av = a_i[i * CS + t];
    float sv = s_i[i * CS + t];
    float r0 = av, r1 = av * av, r2 = sv, r3 = sv * sv;
    #pragma unroll
    for (int o = 16; o > 0; o >>= 1) {
        r0 += __shfl_down_sync(0xffffffffu, r0, o);
        r1 += __shfl_down_sync(0xffffffffu, r1, o);
        r2 += __shfl_down_sync(0xffffffffu, r2, o);
        r3 += __shfl_down_sync(0xffffffffu, r3, o);
    }
    if ((t & 31) == 0) { int w = t >> 5; red[w][0]=r0; red[w][1]=r1; red[w][2]=r2; red[w][3]=r3; }
    __syncthreads();
    if (t == 0) {
        float s0=0, s1=0, s2=0, s3=0;
        #pragma unroll
        for (int w = 0; w < 12; w++) { s0+=red[w][0]; s1+=red[w][1]; s2+=red[w][2]; s3+=red[w][3]; }
        float ma = s0 * (1.0f/CS), ms = s2 * (1.0f/CS);
        float va = s1 * (1.0f/CS) - ma*ma;
        float vs = s3 * (1.0f/CS) - ms*ms;
        bcv[0]=ma; bcv[1]=rsqrtf(va + 1e-5f);
        bcv[2]=ms; bcv[3]=rsqrtf(vs + 1e-5f);
    }
    __syncthreads();
    g_aln[i*CS + t] = (av - bcv[0]) * bcv[1];
    g_sln[i*CS + t] = (sv - bcv[2]) * bcv[3] * lnw[t];
}

// =====================================================================
// Kernel 1: AdaLN. 8-row x 128-col tiles, depth-8 weight prefetch.
// grid (3,128), block 128.
// =====================================================================
#define PF 8
__global__ void __launch_bounds__(128) k_adaln(const float* __restrict__ ws,
                                               const float* __restrict__ bs,
                                               const float* __restrict__ wns) {
    __shared__ __align__(16) float st[CS * 10];
    int i0 = blockIdx.y * 8;
    int t  = threadIdx.x;
    int c  = blockIdx.x * 128 + t;
    #pragma unroll
    for (int r = 0; r < 8; r++)
        for (int kk = t; kk < CS; kk += 128)
            st[kk * 10 + r] = g_sln[(i0 + r) * CS + kk];

    float w1b[PF], w2b[PF];
    #pragma unroll
    for (int p = 0; p < PF; p++) { w1b[p] = ws[p*CS + c]; w2b[p] = wns[p*CS + c]; }
    __syncthreads();

    u64 a1[4], a2[4];
    #pragma unroll
    for (int p = 0; p < 4; p++) { a1[p] = 0ull; a2[p] = 0ull; }
    for (int k0 = 0; k0 < CS; k0 += PF) {
        #pragma unroll
        for (int pp = 0; pp < PF; pp++) {
            int k = k0 + pp;
            float w1 = w1b[pp], w2 = w2b[pp];
            int kn = k + PF;
            if (kn < CS) { w1b[pp] = ws[kn*CS + c]; w2b[pp] = wns[kn*CS + c]; }
            u64 w1p = pk2(w1, w1), w2p = pk2(w2, w2);
            const u64* sp = (const u64*)&st[k * 10];
            #pragma unroll
            for (int p = 0; p < 4; p++) {
                a1[p] = ffma2(sp[p], w1p, a1[p]);
                a2[p] = ffma2(sp[p], w2p, a2[p]);
            }
        }
    }
    float bsc = bs[c];
    #pragma unroll
    for (int p = 0; p < 4; p++) {
        float x0, x1, y0, y1;
        upk2(a1[p], x0, x1); upk2(a2[p], y0, y1);
        int r0 = i0 + 2 * p;
        g_a[r0 * CS + c]       = sigm(x0 + bsc) * g_aln[r0 * CS + c]       + y0;
        g_a[(r0 + 1) * CS + c] = sigm(x1 + bsc) * g_aln[(r0 + 1) * CS + c] + y1;
    }
}

// =====================================================================
// Kernel 2: QKV + gate. 16-row tiles, depth-8 prefetch. grid (3,64,4).
// =====================================================================
__global__ void __launch_bounds__(128) k_qkvg(const float* __restrict__ wq,
                                              const float* __restrict__ bq,
                                              const float* __restrict__ wk,
                                              const float* __restrict__ wv,
                                              const float* __restrict__ wg) {
    __shared__ __align__(16) float at[CS * 18];
    int m  = blockIdx.z;
    int i0 = blockIdx.y * 16;
    int t  = threadIdx.x;
    int c  = blockIdx.x * 128 + t;
    #pragma unroll
    for (int r = 0; r < 16; r++)
        for (int kk = t; kk < CS; kk += 128)
            at[kk * 18 + r] = g_a[(i0 + r) * CS + kk];
    const float* w = (m == 0) ? wq : (m == 1) ? wk : (m == 2) ? wv : wg;
    float wb_[PF];
    #pragma unroll
    for (int p = 0; p < PF; p++) wb_[p] = w[p*CS + c];
    __syncthreads();

    u64 acc[8];
    #pragma unroll
    for (int p = 0; p < 8; p++) acc[p] = 0ull;
    for (int k0 = 0; k0 < CS; k0 += PF) {
        #pragma unroll
        for (int pp = 0; pp < PF; pp++) {
            int k = k0 + pp;
            float wv_ = wb_[pp];
            int kn = k + PF;
            if (kn < CS) wb_[pp] = w[kn*CS + c];
            u64 wp = pk2(wv_, wv_);
            const u64* ap = (const u64*)&at[k * 18];
            #pragma unroll
            for (int p = 0; p < 8; p++) acc[p] = ffma2(ap[p], wp, acc[p]);
        }
    }
    int h = c / DH, d = c - h * DH;
    float bqc = (m == 0) ? bq[c] : 0.0f;
    #pragma unroll
    for (int p = 0; p < 8; p++) {
        float v0, v1; upk2(acc[p], v0, v1);
        int r0 = i0 + 2 * p;
        int idx0 = h * (NSEQ * DH) + r0 * DH + d;
        int idx1 = idx0 + DH;
        if (m == 0)      { g_q[idx0] = (v0 + bqc) * RSQRT_D; g_q[idx1] = (v1 + bqc) * RSQRT_D; }
        else if (m == 1) { g_k[idx0] = v0;                   g_k[idx1] = v1; }
        else if (m == 2) { g_v[idx0] = v0;                   g_v[idx1] = v1; }
        else             { g_g[idx0] = sigm(v0);             g_g[idx1] = sigm(v1); }
    }
}

// =====================================================================
// Kernel 3: pair bias. grid (8,1024), block 128, dyn smem ~74 KB.
// Weight packing preloaded from g_wpk (computed once by k_prep).
// =====================================================================
#define PAIR_SMEM (128*132*4 + NH*64*8 + 2*NH*4)
__global__ void __launch_bounds__(128) k_pair(const float* __restrict__ z) {
    extern __shared__ float sm[];
    float* zs  = sm;                             // 128 x 132 floats (padded)
    u64*   wsm = (u64*)(sm + 128 * 132);         // [h][64]
    float* WH  = (float*)(wsm + NH * 64);
    float* CH  = WH + NH;
    int t  = threadIdx.x;
    int i  = blockIdx.y;
    int j0 = blockIdx.x * 128;

    #pragma unroll
    for (int p = 0; p < 8; p++) wsm[t + p * 128] = g_wpk[t + p * 128];
    if (t < NH)            WH[t]      = g_WH[t];
    else if (t < 2 * NH)   CH[t - NH] = g_CH[t - NH];

    const float4* zg = (const float4*)(z + (size_t)i * (NSEQ * CZ) + (size_t)j0 * CZ);
    #pragma unroll
    for (int p = 0; p < 32; p++) {
        int f = t + p * 128;
        int jl = f >> 5, c4 = f & 31;
        *(float4*)&zs[jl * 132 + c4 * 4] = zg[(size_t)jl * 32 + c4];
    }
    __syncthreads();

    u64 acc[NH];
    #pragma unroll
    for (int h = 0; h < NH; h++) acc[h] = 0ull;
    u64 s2 = 0ull, q2 = 0ull;
    const float* zr = zs + t * 132;
    #pragma unroll 4
    for (int c4 = 0; c4 < 32; c4++) {
        float4 v = *(const float4*)&zr[c4 * 4];
        u64 v01 = pk2(v.x, v.y), v23 = pk2(v.z, v.w);
        s2 = fadd2(s2, fadd2(v01, v23));
        q2 = ffma2(v01, v01, q2);
        q2 = ffma2(v23, v23, q2);
        const u64* base = wsm + 2 * c4;
        #pragma unroll
        for (int h = 0; h < NH; h++) {
            ulonglong2 wv2 = *(const ulonglong2*)(base + h * 64);   // broadcast
            acc[h] = ffma2(v01, wv2.x, acc[h]);
            acc[h] = ffma2(v23, wv2.y, acc[h]);
        }
    }
    float sa, sb, qa, qb;
    upk2(s2, sa, sb); upk2(q2, qa, qb);
    float mean = (sa + sb) * (1.0f / CZ);
    float var  = (qa + qb) * (1.0f / CZ) - mean * mean;
    float rstd = rsqrtf(var + 1e-5f);
    int j = j0 + t;
    float* bo = g_bias + (size_t)i * NSEQ + j;
    #pragma unroll
    for (int h = 0; h < NH; h++) {
        float x0, x1; upk2(acc[h], x0, x1);
        bo[(size_t)h * NN] = ((x0 + x1) - mean * WH[h]) * rstd + CH[h];
    }
}

// =====================================================================
// Kernel 4: flash attention. grid (64,16), block 512, smem 200 KB.
// =====================================================================
#define ATT_SMEM (2 * NSEQ * 25 * 4)
__global__ void __launch_bounds__(512) k_attn() {
    extern __shared__ float sm[];
    float* ks_ = sm;
    float* vs_ = sm + NSEQ * 25;
    int h  = blockIdx.y;
    int i0 = blockIdx.x * 16;
    int t  = threadIdx.x;
    const float* kg = g_k + (size_t)h * NSEQ * DH;
    const float* vg = g_v + (size_t)h * NSEQ * DH;
    for (int e = t; e < NSEQ * DH; e += 512) {
        int j = e / DH, d = e - j * DH;
        ks_[j * 25 + d] = kg[e];
        vs_[j * 25 + d] = vg[e];
    }
    __syncthreads();
    int w = t >> 5, lane = t & 31;
    int i = i0 + w;
    float qv[DH];
    const float* qg = g_q + ((size_t)h * NSEQ + i) * DH;
    #pragma unroll
    for (int d = 0; d < DH; d++) qv[d] = qg[d];
    const float* bp = g_bias + (size_t)h * NN + (size_t)i * NSEQ;
    float m = -1e30f, l = 0.0f, o[DH];
    #pragma unroll
    for (int d = 0; d < DH; d++) o[d] = 0.0f;
    for (int s = 0; s < NSEQ / 32; s++) {
        int j = s * 32 + lane;
        const float* kr = ks_ + j * 25;
        float lg = bp[j];
        #pragma unroll
        for (int d = 0; d < DH; d++) lg += qv[d] * kr[d];
        float mx = lg;
        #pragma unroll
        for (int off = 16; off > 0; off >>= 1)
            mx = fmaxf(mx, __shfl_xor_sync(0xffffffffu, mx, off));
        if (mx > m) {                       // warp-uniform
            float corr = __expf(m - mx);
            l *= corr;
            #pragma unroll
            for (int d = 0; d < DH; d++) o[d] *= corr;
            m = mx;
        }
        float p = __expf(lg - m);
        l += p;
        const float* vr = vs_ + j * 25;
        #pragma unroll
        for (int d = 0; d < DH; d++) o[d] += p * vr[d];
    }
    #pragma unroll
    for (int off = 16; off > 0; off >>= 1) l += __shfl_xor_sync(0xffffffffu, l, off);
    #pragma unroll
    for (int d = 0; d < DH; d++) {
        #pragma unroll
        for (int off = 16; off > 0; off >>= 1)
            o[d] += __shfl_xor_sync(0xffffffffu, o[d], off);
    }
    if (lane == 0) {
        float inv = 1.0f / l;
        const float* gg = g_g + ((size_t)h * NSEQ + i) * DH;
        float* op = g_o + (size_t)i * HC + h * DH;
        #pragma unroll
        for (int d = 0; d < DH; d++) op[d] = o[d] * inv * gg[d];
    }
}

// =====================================================================
// Kernel 5: out = sigmoid(s_i@ws2 + bs2) * (o@wo). 8-row tiles,
// depth-8 prefetch. grid (3,128), block 128.
// =====================================================================
__global__ void __launch_bounds__(128) k_out(const float* __restrict__ s_i,
                                             const float* __restrict__ ws2,
                                             const float* __restrict__ bs2,
                                             const float* __restrict__ wo,
                                             float* __restrict__ out) {
    __shared__ __align__(16) float st[CS * 10];
    __shared__ __align__(16) float ot[CS * 10];
    int i0 = blockIdx.y * 8;
    int t  = threadIdx.x;
    int c  = blockIdx.x * 128 + t;
    #pragma unroll
    for (int r = 0; r < 8; r++)
        for (int kk = t; kk < CS; kk += 128) {
            st[kk * 10 + r] = s_i[(i0 + r) * CS + kk];
            ot[kk * 10 + r] = g_o[(i0 + r) * CS + kk];
        }
    float w1b[PF], w2b[PF];
    #pragma unroll
    for (int p = 0; p < PF; p++) { w1b[p] = ws2[p*CS + c]; w2b[p] = wo[p*CS + c]; }
    __syncthreads();

    u64 a1[4], a2[4];
    #pragma unroll
    for (int p = 0; p < 4; p++) { a1[p] = 0ull; a2[p] = 0ull; }
    for (int k0 = 0; k0 < CS; k0 += PF) {
        #pragma unroll
        for (int pp = 0; pp < PF; pp++) {
            int k = k0 + pp;
            float w1 = w1b[pp], w2 = w2b[pp];
            int kn = k + PF;
            if (kn < CS) { w1b[pp] = ws2[kn*CS + c]; w2b[pp] = wo[kn*CS + c]; }
            u64 w1p = pk2(w1, w1), w2p = pk2(w2, w2);
            const u64* sp = (const u64*)&st[k * 10];
            const u64* op = (const u64*)&ot[k * 10];
            #pragma unroll
            for (int p = 0; p < 4; p++) {
                a1[p] = ffma2(sp[p], w1p, a1[p]);
                a2[p] = ffma2(op[p], w2p, a2[p]);
            }
        }
    }
    float bsc = bs2[c];
    #pragma unroll
    for (int p = 0; p < 4; p++) {
        float x0, x1, y0, y1;
        upk2(a1[p], x0, x1); upk2(a2[p], y0, y1);
        int r0 = i0 + 2 * p;
        out[r0 * CS + c]       = sigm(x0 + bsc) * y0;
        out[(r0 + 1) * CS + c] = sigm(x1 + bsc) * y1;
    }
}

// =====================================================================
extern "C" void kernel_launch(void* const* d_in, const int* in_sizes, int n_in,
                              void* d_out, int out_size) {
    const float* a_i   = (const float*)d_in[0];
    const float* s_i   = (const float*)d_in[1];
    const float* z     = (const float*)d_in[2];
    const float* lns_w = (const float*)d_in[3];
    const float* aws   = (const float*)d_in[4];
    const float* abs_  = (const float*)d_in[5];
    const float* awns  = (const float*)d_in[6];
    const float* wq    = (const float*)d_in[7];
    const float* bq    = (const float*)d_in[8];
    const float* wk    = (const float*)d_in[9];
    const float* wv    = (const float*)d_in[10];
    const float* lnb_w = (const float*)d_in[11];
    const float* lnb_b = (const float*)d_in[12];
    const float* wb    = (const float*)d_in[13];
    const float* wg    = (const float*)d_in[14];
    const float* wo    = (const float*)d_in[15];
    const float* ws2   = (const float*)d_in[16];
    const float* bs2   = (const float*)d_in[17];
    float* out = (float*)d_out;

    cudaFuncSetAttribute(k_pair, cudaFuncAttributeMaxDynamicSharedMemorySize, PAIR_SMEM);
    cudaFuncSetAttribute(k_attn, cudaFuncAttributeMaxDynamicSharedMemorySize, ATT_SMEM);

    k_prep<<<1, 128>>>(lnb_w, lnb_b, wb);
    k_ln<<<NSEQ, CS>>>(a_i, s_i, lns_w);
    k_pair<<<dim3(8, NSEQ), 128, PAIR_SMEM>>>(z);
    k_adaln<<<dim3(3, 128), 128>>>(aws, abs_, awns);
    k_qkvg<<<dim3(3, 64, 4), 128>>>(wq, bq, wk, wv, wg);
    k_attn<<<dim3(64, 16), 512, ATT_SMEM>>>();
    k_out<<<dim3(3, 128), 128>>>(s_i, ws2, bs2, wo, out);
}

// round 5
// speedup vs baseline: 1.5161x; 1.1172x over previous
#include <cuda_runtime.h>
#include <cuda_bf16.h>
#include <math.h>

#define NSEQ 1024
#define CS   384
#define CZ   128
#define NH   16
#define DH   24
#define HC   384
#define NN   (NSEQ*NSEQ)
#define RSQRT_D 0.2041241452319315f

typedef unsigned long long u64;

__device__ __forceinline__ u64 pk2(float a, float b) {
    u64 r; asm("mov.b64 %0,{%1,%2};" : "=l"(r) : "f"(a), "f"(b)); return r;
}
__device__ __forceinline__ void upk2(u64 v, float& a, float& b) {
    asm("mov.b64 {%0,%1},%2;" : "=f"(a), "=f"(b) : "l"(v));
}
__device__ __forceinline__ u64 ffma2(u64 a, u64 b, u64 c) {
    u64 d; asm("fma.rn.f32x2 %0,%1,%2,%3;" : "=l"(d) : "l"(a), "l"(b), "l"(c)); return d;
}
__device__ __forceinline__ u64 fadd2(u64 a, u64 b) {
    u64 d; asm("add.rn.f32x2 %0,%1,%2;" : "=l"(d) : "l"(a), "l"(b)); return d;
}
__device__ __forceinline__ float sigm(float x) { return 1.0f / (1.0f + __expf(-x)); }

// ------------- scratch (static device globals) -------------
__device__ float g_aln[NSEQ * CS];
__device__ float g_sln[NSEQ * CS];
__device__ float g_a  [NSEQ * CS];
__device__ float g_q  [NH * NSEQ * DH];
__device__ float g_k  [NH * NSEQ * DH];
__device__ float g_v  [NH * NSEQ * DH];
__device__ float g_g  [NH * NSEQ * DH];
__device__ float g_bias[(size_t)NH * NN];   // [h][i][j], 64 MB
__device__ float g_o  [NSEQ * HC];
__device__ u64   g_wpk[NH * 64];
__device__ float g_WH[NH];
__device__ float g_CH[NH];

// =====================================================================
// Kernel P: one-time prep of pair-bias weights.
// =====================================================================
__global__ void __launch_bounds__(128) k_prep(const float* __restrict__ lnw,
                                              const float* __restrict__ lnb,
                                              const float* __restrict__ wb) {
    int t = threadIdx.x;
    for (int idx = t; idx < NH * 64; idx += 128) {
        int h = idx >> 6, c2 = idx & 63;
        g_wpk[idx] = pk2(lnw[2*c2]     * wb[(2*c2)     * NH + h],
                         lnw[2*c2 + 1] * wb[(2*c2 + 1) * NH + h]);
    }
    if (t < NH) {
        float W = 0, C = 0;
        #pragma unroll 4
        for (int cc = 0; cc < CZ; cc++) {
            float wv = wb[cc * NH + t];
            W += lnw[cc] * wv; C += lnb[cc] * wv;
        }
        g_WH[t] = W; g_CH[t] = C;
    }
}

// =====================================================================
// Kernel 0: row layer norms of a_i and s_i.  grid 1024, block 384.
// =====================================================================
__global__ void __launch_bounds__(384) k_ln(const float* __restrict__ a_i,
                                            const float* __restrict__ s_i,
                                            const float* __restrict__ lnw) {
    __shared__ float red[12][4];
    __shared__ float bcv[4];
    int i = blockIdx.x, t = threadIdx.x;
    float av = a_i[i * CS + t];
    float sv = s_i[i * CS + t];
    float r0 = av, r1 = av * av, r2 = sv, r3 = sv * sv;
    #pragma unroll
    for (int o = 16; o > 0; o >>= 1) {
        r0 += __shfl_down_sync(0xffffffffu, r0, o);
        r1 += __shfl_down_sync(0xffffffffu, r1, o);
        r2 += __shfl_down_sync(0xffffffffu, r2, o);
        r3 += __shfl_down_sync(0xffffffffu, r3, o);
    }
    if ((t & 31) == 0) { int w = t >> 5; red[w][0]=r0; red[w][1]=r1; red[w][2]=r2; red[w][3]=r3; }
    __syncthreads();
    if (t == 0) {
        float s0=0, s1=0, s2=0, s3=0;
        #pragma unroll
        for (int w = 0; w < 12; w++) { s0+=red[w][0]; s1+=red[w][1]; s2+=red[w][2]; s3+=red[w][3]; }
        float ma = s0 * (1.0f/CS), ms = s2 * (1.0f/CS);
        float va = s1 * (1.0f/CS) - ma*ma;
        float vs = s3 * (1.0f/CS) - ms*ms;
        bcv[0]=ma; bcv[1]=rsqrtf(va + 1e-5f);
        bcv[2]=ms; bcv[3]=rsqrtf(vs + 1e-5f);
    }
    __syncthreads();
    g_aln[i*CS + t] = (av - bcv[0]) * bcv[1];
    g_sln[i*CS + t] = (sv - bcv[2]) * bcv[3] * lnw[t];
}

// =====================================================================
// Kernel 1: AdaLN. 16-row x 128-col tiles, block 256 (two 8-row halves),
// double-buffered smem weights (16-k chunks). grid (3,64). Dyn smem 62 KB.
// =====================================================================
#define ST20 20
#define ADA_SMEM ((CS*ST20 + 2*2*16*128) * 4)
__global__ void __launch_bounds__(256) k_adaln(const float* __restrict__ ws,
                                               const float* __restrict__ bs,
                                               const float* __restrict__ wns) {
    extern __shared__ float dsm[];
    float* st  = dsm;                 // act transposed: [k*20 + r], r<16
    float* wbf = dsm + CS * ST20;     // [buf][mat][16][128]
    int t  = threadIdx.x;
    int tx = t & 127, ty = t >> 7;
    int i0 = blockIdx.y * 16;
    int c0 = blockIdx.x * 128;
    int c  = c0 + tx;

    for (int r = 0; r < 16; r++)
        for (int kk = t; kk < CS; kk += 256)
            st[kk * ST20 + r] = g_sln[(i0 + r) * CS + kk];

    const int NC = CS / 16;           // 24 chunks
    float4 ldr[4];
    // prologue: chunk 0
    #pragma unroll
    for (int iL = 0; iL < 4; iL++) {
        int idx = t + iL * 256;
        int mat = idx >> 9, rem = idx & 511, kr = rem >> 5, c4 = rem & 31;
        const float* w = mat ? wns : ws;
        ldr[iL] = *(const float4*)(w + (size_t)kr * CS + c0 + c4 * 4);
    }
    #pragma unroll
    for (int iL = 0; iL < 4; iL++) {
        int idx = t + iL * 256;
        int mat = idx >> 9, rem = idx & 511, kr = rem >> 5, c4 = rem & 31;
        *(float4*)&wbf[mat * 2048 + kr * 128 + c4 * 4] = ldr[iL];
    }
    __syncthreads();

    u64 a1[4], a2[4];
    #pragma unroll
    for (int p = 0; p < 4; p++) { a1[p] = 0ull; a2[p] = 0ull; }
    for (int ch = 0; ch < NC; ch++) {
        int cur = ch & 1;
        if (ch + 1 < NC) {
            int k0 = (ch + 1) * 16;
            #pragma unroll
            for (int iL = 0; iL < 4; iL++) {
                int idx = t + iL * 256;
                int mat = idx >> 9, rem = idx & 511, kr = rem >> 5, c4 = rem & 31;
                const float* w = mat ? wns : ws;
                ldr[iL] = *(const float4*)(w + (size_t)(k0 + kr) * CS + c0 + c4 * 4);
            }
        }
        #pragma unroll
        for (int kk = 0; kk < 16; kk++) {
            int k = ch * 16 + kk;
            float w1 = wbf[cur * 4096 + kk * 128 + tx];
            float w2 = wbf[cur * 4096 + 2048 + kk * 128 + tx];
            u64 w1p = pk2(w1, w1), w2p = pk2(w2, w2);
            const u64* sp = (const u64*)&st[k * ST20 + ty * 8];
            #pragma unroll
            for (int p = 0; p < 4; p++) {
                a1[p] = ffma2(sp[p], w1p, a1[p]);
                a2[p] = ffma2(sp[p], w2p, a2[p]);
            }
        }
        if (ch + 1 < NC) {
            int nb = (ch + 1) & 1;
            #pragma unroll
            for (int iL = 0; iL < 4; iL++) {
                int idx = t + iL * 256;
                int mat = idx >> 9, rem = idx & 511, kr = rem >> 5, c4 = rem & 31;
                *(float4*)&wbf[nb * 4096 + mat * 2048 + kr * 128 + c4 * 4] = ldr[iL];
            }
        }
        __syncthreads();
    }
    float bsc = bs[c];
    #pragma unroll
    for (int p = 0; p < 4; p++) {
        float x0, x1, y0, y1;
        upk2(a1[p], x0, x1); upk2(a2[p], y0, y1);
        int r0 = i0 + ty * 8 + 2 * p;
        g_a[r0 * CS + c]       = sigm(x0 + bsc) * g_aln[r0 * CS + c]       + y0;
        g_a[(r0 + 1) * CS + c] = sigm(x1 + bsc) * g_aln[(r0 + 1) * CS + c] + y1;
    }
}

// =====================================================================
// Kernel 2: QKV + gate. Same scheme, 1 matrix/block. grid (3,64,4),
// block 256, static smem ~46 KB.
// =====================================================================
__global__ void __launch_bounds__(256) k_qkvg(const float* __restrict__ wq,
                                              const float* __restrict__ bq,
                                              const float* __restrict__ wk,
                                              const float* __restrict__ wv,
                                              const float* __restrict__ wg) {
    __shared__ __align__(16) float st[CS * ST20];
    __shared__ __align__(16) float wbf[2 * 16 * 128];
    int t  = threadIdx.x;
    int tx = t & 127, ty = t >> 7;
    int m  = blockIdx.z;
    int i0 = blockIdx.y * 16;
    int c0 = blockIdx.x * 128;
    int c  = c0 + tx;
    const float* w = (m == 0) ? wq : (m == 1) ? wk : (m == 2) ? wv : wg;

    for (int r = 0; r < 16; r++)
        for (int kk = t; kk < CS; kk += 256)
            st[kk * ST20 + r] = g_a[(i0 + r) * CS + kk];

    const int NC = CS / 16;
    float4 ldr[2];
    #pragma unroll
    for (int iL = 0; iL < 2; iL++) {
        int idx = t + iL * 256;
        int kr = idx >> 5, c4 = idx & 31;
        ldr[iL] = *(const float4*)(w + (size_t)kr * CS + c0 + c4 * 4);
    }
    #pragma unroll
    for (int iL = 0; iL < 2; iL++) {
        int idx = t + iL * 256;
        int kr = idx >> 5, c4 = idx & 31;
        *(float4*)&wbf[kr * 128 + c4 * 4] = ldr[iL];
    }
    __syncthreads();

    u64 acc[4];
    #pragma unroll
    for (int p = 0; p < 4; p++) acc[p] = 0ull;
    for (int ch = 0; ch < NC; ch++) {
        int cur = ch & 1;
        if (ch + 1 < NC) {
            int k0 = (ch + 1) * 16;
            #pragma unroll
            for (int iL = 0; iL < 2; iL++) {
                int idx = t + iL * 256;
                int kr = idx >> 5, c4 = idx & 31;
                ldr[iL] = *(const float4*)(w + (size_t)(k0 + kr) * CS + c0 + c4 * 4);
            }
        }
        #pragma unroll
        for (int kk = 0; kk < 16; kk++) {
            int k = ch * 16 + kk;
            float wv_ = wbf[cur * 2048 + kk * 128 + tx];
            u64 wp = pk2(wv_, wv_);
            const u64* sp = (const u64*)&st[k * ST20 + ty * 8];
            #pragma unroll
            for (int p = 0; p < 4; p++) acc[p] = ffma2(sp[p], wp, acc[p]);
        }
        if (ch + 1 < NC) {
            int nb = (ch + 1) & 1;
            #pragma unroll
            for (int iL = 0; iL < 2; iL++) {
                int idx = t + iL * 256;
                int kr = idx >> 5, c4 = idx & 31;
                *(float4*)&wbf[nb * 2048 + kr * 128 + c4 * 4] = ldr[iL];
            }
        }
        __syncthreads();
    }
    int h = c / DH, d = c - h * DH;
    float bqc = (m == 0) ? bq[c] : 0.0f;
    #pragma unroll
    for (int p = 0; p < 4; p++) {
        float v0, v1; upk2(acc[p], v0, v1);
        int r0 = i0 + ty * 8 + 2 * p;
        int idx0 = h * (NSEQ * DH) + r0 * DH + d;
        int idx1 = idx0 + DH;
        if (m == 0)      { g_q[idx0] = (v0 + bqc) * RSQRT_D; g_q[idx1] = (v1 + bqc) * RSQRT_D; }
        else if (m == 1) { g_k[idx0] = v0;                   g_k[idx1] = v1; }
        else if (m == 2) { g_v[idx0] = v0;                   g_v[idx1] = v1; }
        else             { g_g[idx0] = sigm(v0);             g_g[idx1] = sigm(v1); }
    }
}

// =====================================================================
// Kernel 3: pair bias. grid (8,1024), block 128, dyn smem ~74 KB.
// =====================================================================
#define PAIR_SMEM (128*132*4 + NH*64*8 + 2*NH*4)
__global__ void __launch_bounds__(128) k_pair(const float* __restrict__ z) {
    extern __shared__ float sm[];
    float* zs  = sm;                             // 128 x 132 floats (padded)
    u64*   wsm = (u64*)(sm + 128 * 132);         // [h][64]
    float* WH  = (float*)(wsm + NH * 64);
    float* CH  = WH + NH;
    int t  = threadIdx.x;
    int i  = blockIdx.y;
    int j0 = blockIdx.x * 128;

    #pragma unroll
    for (int p = 0; p < 8; p++) wsm[t + p * 128] = g_wpk[t + p * 128];
    if (t < NH)            WH[t]      = g_WH[t];
    else if (t < 2 * NH)   CH[t - NH] = g_CH[t - NH];

    const float4* zg = (const float4*)(z + (size_t)i * (NSEQ * CZ) + (size_t)j0 * CZ);
    #pragma unroll
    for (int p = 0; p < 32; p++) {
        int f = t + p * 128;
        int jl = f >> 5, c4 = f & 31;
        *(float4*)&zs[jl * 132 + c4 * 4] = zg[(size_t)jl * 32 + c4];
    }
    __syncthreads();

    u64 acc[NH];
    #pragma unroll
    for (int h = 0; h < NH; h++) acc[h] = 0ull;
    u64 s2 = 0ull, q2 = 0ull;
    const float* zr = zs + t * 132;
    #pragma unroll 4
    for (int c4 = 0; c4 < 32; c4++) {
        float4 v = *(const float4*)&zr[c4 * 4];
        u64 v01 = pk2(v.x, v.y), v23 = pk2(v.z, v.w);
        s2 = fadd2(s2, fadd2(v01, v23));
        q2 = ffma2(v01, v01, q2);
        q2 = ffma2(v23, v23, q2);
        const u64* base = wsm + 2 * c4;
        #pragma unroll
        for (int h = 0; h < NH; h++) {
            ulonglong2 wv2 = *(const ulonglong2*)(base + h * 64);   // broadcast
            acc[h] = ffma2(v01, wv2.x, acc[h]);
            acc[h] = ffma2(v23, wv2.y, acc[h]);
        }
    }
    float sa, sb, qa, qb;
    upk2(s2, sa, sb); upk2(q2, qa, qb);
    float mean = (sa + sb) * (1.0f / CZ);
    float var  = (qa + qb) * (1.0f / CZ) - mean * mean;
    float rstd = rsqrtf(var + 1e-5f);
    int j = j0 + t;
    float* bo = g_bias + (size_t)i * NSEQ + j;
    #pragma unroll
    for (int h = 0; h < NH; h++) {
        float x0, x1; upk2(acc[h], x0, x1);
        bo[(size_t)h * NN] = ((x0 + x1) - mean * WH[h]) * rstd + CH[h];
    }
}

// =====================================================================
// Kernel 4: two-pass per-lane flash attention. grid (64,16), block 512.
// Pass 1: all 32 logits in regs (independent bias LDGs -> MLP), one
// warp max-reduce. Pass 2: exp + PV. No per-iter shfl / rescale.
// =====================================================================
#define ATT_SMEM (2 * NSEQ * 25 * 4)
__global__ void __launch_bounds__(512) k_attn() {
    extern __shared__ float sm[];
    float* ks_ = sm;
    float* vs_ = sm + NSEQ * 25;
    int h  = blockIdx.y;
    int i0 = blockIdx.x * 16;
    int t  = threadIdx.x;
    const float* kg = g_k + (size_t)h * NSEQ * DH;
    const float* vg = g_v + (size_t)h * NSEQ * DH;
    for (int e = t; e < NSEQ * DH; e += 512) {
        int j = e / DH, d = e - j * DH;
        ks_[j * 25 + d] = kg[e];
        vs_[j * 25 + d] = vg[e];
    }
    __syncthreads();
    int w = t >> 5, lane = t & 31;
    int i = i0 + w;
    float qv[DH];
    const float* qg = g_q + ((size_t)h * NSEQ + i) * DH;
    #pragma unroll
    for (int d = 0; d < DH; d++) qv[d] = qg[d];
    const float* bp = g_bias + (size_t)h * NN + (size_t)i * NSEQ;

    // pass 1: logits
    float lgs[32];
    float mx = -1e30f;
    #pragma unroll
    for (int s = 0; s < 32; s++) {
        int j = s * 32 + lane;
        const float* kr = ks_ + j * 25;
        float lg = bp[j];
        #pragma unroll
        for (int d = 0; d < DH; d++) lg += qv[d] * kr[d];
        lgs[s] = lg;
        mx = fmaxf(mx, lg);
    }
    #pragma unroll
    for (int off = 16; off > 0; off >>= 1)
        mx = fmaxf(mx, __shfl_xor_sync(0xffffffffu, mx, off));

    // pass 2
    float l = 0.0f, o[DH];
    #pragma unroll
    for (int d = 0; d < DH; d++) o[d] = 0.0f;
    #pragma unroll
    for (int s = 0; s < 32; s++) {
        float p = __expf(lgs[s] - mx);
        l += p;
        const float* vr = vs_ + (s * 32 + lane) * 25;
        #pragma unroll
        for (int d = 0; d < DH; d++) o[d] += p * vr[d];
    }
    #pragma unroll
    for (int off = 16; off > 0; off >>= 1) l += __shfl_xor_sync(0xffffffffu, l, off);
    #pragma unroll
    for (int d = 0; d < DH; d++) {
        #pragma unroll
        for (int off = 16; off > 0; off >>= 1)
            o[d] += __shfl_xor_sync(0xffffffffu, o[d], off);
    }
    if (lane == 0) {
        float inv = 1.0f / l;
        const float* gg = g_g + ((size_t)h * NSEQ + i) * DH;
        float* op = g_o + (size_t)i * HC + h * DH;
        #pragma unroll
        for (int d = 0; d < DH; d++) op[d] = o[d] * inv * gg[d];
    }
}

// =====================================================================
// Kernel 5: out = sigmoid(s_i@ws2 + bs2) * (o@wo). Same GEMM scheme,
// two act tiles. grid (3,64), block 256, dyn smem ~92 KB.
// =====================================================================
#define OUT_SMEM ((2*CS*ST20 + 2*2*16*128) * 4)
__global__ void __launch_bounds__(256) k_out(const float* __restrict__ s_i,
                                             const float* __restrict__ ws2,
                                             const float* __restrict__ bs2,
                                             const float* __restrict__ wo,
                                             float* __restrict__ out) {
    extern __shared__ float dsm[];
    float* st  = dsm;
    float* ot  = dsm + CS * ST20;
    float* wbf = dsm + 2 * CS * ST20;
    int t  = threadIdx.x;
    int tx = t & 127, ty = t >> 7;
    int i0 = blockIdx.y * 16;
    int c0 = blockIdx.x * 128;
    int c  = c0 + tx;

    for (int r = 0; r < 16; r++)
        for (int kk = t; kk < CS; kk += 256) {
            st[kk * ST20 + r] = s_i[(i0 + r) * CS + kk];
            ot[kk * ST20 + r] = g_o[(i0 + r) * CS + kk];
        }

    const int NC = CS / 16;
    float4 ldr[4];
    #pragma unroll
    for (int iL = 0; iL < 4; iL++) {
        int idx = t + iL * 256;
        int mat = idx >> 9, rem = idx & 511, kr = rem >> 5, c4 = rem & 31;
        const float* w = mat ? wo : ws2;
        ldr[iL] = *(const float4*)(w + (size_t)kr * CS + c0 + c4 * 4);
    }
    #pragma unroll
    for (int iL = 0; iL < 4; iL++) {
        int idx = t + iL * 256;
        int mat = idx >> 9, rem = idx & 511, kr = rem >> 5, c4 = rem & 31;
        *(float4*)&wbf[mat * 2048 + kr * 128 + c4 * 4] = ldr[iL];
    }
    __syncthreads();

    u64 a1[4], a2[4];
    #pragma unroll
    for (int p = 0; p < 4; p++) { a1[p] = 0ull; a2[p] = 0ull; }
    for (int ch = 0; ch < NC; ch++) {
        int cur = ch & 1;
        if (ch + 1 < NC) {
            int k0 = (ch + 1) * 16;
            #pragma unroll
            for (int iL = 0; iL < 4; iL++) {
                int idx = t + iL * 256;
                int mat = idx >> 9, rem = idx & 511, kr = rem >> 5, c4 = rem & 31;
                const float* w = mat ? wo : ws2;
                ldr[iL] = *(const float4*)(w + (size_t)(k0 + kr) * CS + c0 + c4 * 4);
            }
        }
        #pragma unroll
        for (int kk = 0; kk < 16; kk++) {
            int k = ch * 16 + kk;
            float w1 = wbf[cur * 4096 + kk * 128 + tx];
            float w2 = wbf[cur * 4096 + 2048 + kk * 128 + tx];
            u64 w1p = pk2(w1, w1), w2p = pk2(w2, w2);
            const u64* sp = (const u64*)&st[k * ST20 + ty * 8];
            const u64* op = (const u64*)&ot[k * ST20 + ty * 8];
            #pragma unroll
            for (int p = 0; p < 4; p++) {
                a1[p] = ffma2(sp[p], w1p, a1[p]);
                a2[p] = ffma2(op[p], w2p, a2[p]);
            }
        }
        if (ch + 1 < NC) {
            int nb = (ch + 1) & 1;
            #pragma unroll
            for (int iL = 0; iL < 4; iL++) {
                int idx = t + iL * 256;
                int mat = idx >> 9, rem = idx & 511, kr = rem >> 5, c4 = rem & 31;
                *(float4*)&wbf[nb * 4096 + mat * 2048 + kr * 128 + c4 * 4] = ldr[iL];
            }
        }
        __syncthreads();
    }
    float bsc = bs2[c];
    #pragma unroll
    for (int p = 0; p < 4; p++) {
        float x0, x1, y0, y1;
        upk2(a1[p], x0, x1); upk2(a2[p], y0, y1);
        int r0 = i0 + ty * 8 + 2 * p;
        out[r0 * CS + c]       = sigm(x0 + bsc) * y0;
        out[(r0 + 1) * CS + c] = sigm(x1 + bsc) * y1;
    }
}

// =====================================================================
extern "C" void kernel_launch(void* const* d_in, const int* in_sizes, int n_in,
                              void* d_out, int out_size) {
    const float* a_i   = (const float*)d_in[0];
    const float* s_i   = (const float*)d_in[1];
    const float* z     = (const float*)d_in[2];
    const float* lns_w = (const float*)d_in[3];
    const float* aws   = (const float*)d_in[4];
    const float* abs_  = (const float*)d_in[5];
    const float* awns  = (const float*)d_in[6];
    const float* wq    = (const float*)d_in[7];
    const float* bq    = (const float*)d_in[8];
    const float* wk    = (const float*)d_in[9];
    const float* wv    = (const float*)d_in[10];
    const float* lnb_w = (const float*)d_in[11];
    const float* lnb_b = (const float*)d_in[12];
    const float* wb    = (const float*)d_in[13];
    const float* wg    = (const float*)d_in[14];
    const float* wo    = (const float*)d_in[15];
    const float* ws2   = (const float*)d_in[16];
    const float* bs2   = (const float*)d_in[17];
    float* out = (float*)d_out;

    cudaFuncSetAttribute(k_pair,  cudaFuncAttributeMaxDynamicSharedMemorySize, PAIR_SMEM);
    cudaFuncSetAttribute(k_attn,  cudaFuncAttributeMaxDynamicSharedMemorySize, ATT_SMEM);
    cudaFuncSetAttribute(k_adaln, cudaFuncAttributeMaxDynamicSharedMemorySize, ADA_SMEM);
    cudaFuncSetAttribute(k_out,   cudaFuncAttributeMaxDynamicSharedMemorySize, OUT_SMEM);

    k_prep<<<1, 128>>>(lnb_w, lnb_b, wb);
    k_ln<<<NSEQ, CS>>>(a_i, s_i, lns_w);
    k_pair<<<dim3(8, NSEQ), 128, PAIR_SMEM>>>(z);
    k_adaln<<<dim3(3, 64), 256, ADA_SMEM>>>(aws, abs_, awns);
    k_qkvg<<<dim3(3, 64, 4), 256>>>(wq, bq, wk, wv, wg);
    k_attn<<<dim3(64, 16), 512, ATT_SMEM>>>();
    k_out<<<dim3(3, 64), 256, OUT_SMEM>>>(s_i, ws2, bs2, wo, out);
}

// round 6
// speedup vs baseline: 1.6445x; 1.0847x over previous
#include <cuda_runtime.h>
#include <cuda_bf16.h>
#include <math.h>

#define NSEQ 1024
#define CS   384
#define CZ   128
#define NH   16
#define DH   24
#define HC   384
#define NN   (NSEQ*NSEQ)
#define RSQRT_D 0.2041241452319315f

typedef unsigned long long u64;

__device__ __forceinline__ u64 pk2(float a, float b) {
    u64 r; asm("mov.b64 %0,{%1,%2};" : "=l"(r) : "f"(a), "f"(b)); return r;
}
__device__ __forceinline__ void upk2(u64 v, float& a, float& b) {
    asm("mov.b64 {%0,%1},%2;" : "=f"(a), "=f"(b) : "l"(v));
}
__device__ __forceinline__ u64 ffma2(u64 a, u64 b, u64 c) {
    u64 d; asm("fma.rn.f32x2 %0,%1,%2,%3;" : "=l"(d) : "l"(a), "l"(b), "l"(c)); return d;
}
__device__ __forceinline__ u64 fadd2(u64 a, u64 b) {
    u64 d; asm("add.rn.f32x2 %0,%1,%2;" : "=l"(d) : "l"(a), "l"(b)); return d;
}
__device__ __forceinline__ float sigm(float x) { return 1.0f / (1.0f + __expf(-x)); }

// ------------- scratch (static device globals) -------------
__device__ float g_aln[NSEQ * CS];
__device__ float g_sln[NSEQ * CS];
__device__ float g_a  [NSEQ * CS];
__device__ float g_q  [NH * NSEQ * DH];
__device__ float g_k  [NH * NSEQ * DH];
__device__ float g_v  [NH * NSEQ * DH];
__device__ float g_g  [NH * NSEQ * DH];
__device__ float g_bias[(size_t)NH * NN];   // [h][i][j], 64 MB
__device__ float g_o  [NSEQ * HC];
__device__ float g_gate[NSEQ * CS];         // sigmoid(s_i@ws2+bs2)
__device__ u64   g_wpk[NH * 64];
__device__ float g_WH[NH];
__device__ float g_CH[NH];

// =====================================================================
// Kernel P: one-time prep of pair-bias weights.
// =====================================================================
__global__ void __launch_bounds__(128) k_prep(const float* __restrict__ lnw,
                                              const float* __restrict__ lnb,
                                              const float* __restrict__ wb) {
    int t = threadIdx.x;
    for (int idx = t; idx < NH * 64; idx += 128) {
        int h = idx >> 6, c2 = idx & 63;
        g_wpk[idx] = pk2(lnw[2*c2]     * wb[(2*c2)     * NH + h],
                         lnw[2*c2 + 1] * wb[(2*c2 + 1) * NH + h]);
    }
    if (t < NH) {
        float W = 0, C = 0;
        #pragma unroll 4
        for (int cc = 0; cc < CZ; cc++) {
            float wv = wb[cc * NH + t];
            W += lnw[cc] * wv; C += lnb[cc] * wv;
        }
        g_WH[t] = W; g_CH[t] = C;
    }
}

// =====================================================================
// Kernel 0: row layer norms of a_i and s_i.  grid 1024, block 384.
// =====================================================================
__global__ void __launch_bounds__(384) k_ln(const float* __restrict__ a_i,
                                            const float* __restrict__ s_i,
                                            const float* __restrict__ lnw) {
    __shared__ float red[12][4];
    __shared__ float bcv[4];
    int i = blockIdx.x, t = threadIdx.x;
    float av = a_i[i * CS + t];
    float sv = s_i[i * CS + t];
    float r0 = av, r1 = av * av, r2 = sv, r3 = sv * sv;
    #pragma unroll
    for (int o = 16; o > 0; o >>= 1) {
        r0 += __shfl_down_sync(0xffffffffu, r0, o);
        r1 += __shfl_down_sync(0xffffffffu, r1, o);
        r2 += __shfl_down_sync(0xffffffffu, r2, o);
        r3 += __shfl_down_sync(0xffffffffu, r3, o);
    }
    if ((t & 31) == 0) { int w = t >> 5; red[w][0]=r0; red[w][1]=r1; red[w][2]=r2; red[w][3]=r3; }
    __syncthreads();
    if (t == 0) {
        float s0=0, s1=0, s2=0, s3=0;
        #pragma unroll
        for (int w = 0; w < 12; w++) { s0+=red[w][0]; s1+=red[w][1]; s2+=red[w][2]; s3+=red[w][3]; }
        float ma = s0 * (1.0f/CS), ms = s2 * (1.0f/CS);
        float va = s1 * (1.0f/CS) - ma*ma;
        float vs = s3 * (1.0f/CS) - ms*ms;
        bcv[0]=ma; bcv[1]=rsqrtf(va + 1e-5f);
        bcv[2]=ms; bcv[3]=rsqrtf(vs + 1e-5f);
    }
    __syncthreads();
    g_aln[i*CS + t] = (av - bcv[0]) * bcv[1];
    g_sln[i*CS + t] = (sv - bcv[2]) * bcv[3] * lnw[t];
}

// =====================================================================
// Kernel 1: AdaLN. 16-row x 128-col tiles, block 256, double-buffered
// smem weights. grid (3,64). Dyn smem 62 KB.
// =====================================================================
#define ST20 20
#define ADA_SMEM ((CS*ST20 + 2*2*16*128) * 4)
__global__ void __launch_bounds__(256) k_adaln(const float* __restrict__ ws,
                                               const float* __restrict__ bs,
                                               const float* __restrict__ wns) {
    extern __shared__ float dsm[];
    float* st  = dsm;
    float* wbf = dsm + CS * ST20;
    int t  = threadIdx.x;
    int tx = t & 127, ty = t >> 7;
    int i0 = blockIdx.y * 16;
    int c0 = blockIdx.x * 128;
    int c  = c0 + tx;

    for (int r = 0; r < 16; r++)
        for (int kk = t; kk < CS; kk += 256)
            st[kk * ST20 + r] = g_sln[(i0 + r) * CS + kk];

    const int NC = CS / 16;
    float4 ldr[4];
    #pragma unroll
    for (int iL = 0; iL < 4; iL++) {
        int idx = t + iL * 256;
        int mat = idx >> 9, rem = idx & 511, kr = rem >> 5, c4 = rem & 31;
        const float* w = mat ? wns : ws;
        ldr[iL] = *(const float4*)(w + (size_t)kr * CS + c0 + c4 * 4);
    }
    #pragma unroll
    for (int iL = 0; iL < 4; iL++) {
        int idx = t + iL * 256;
        int mat = idx >> 9, rem = idx & 511, kr = rem >> 5, c4 = rem & 31;
        *(float4*)&wbf[mat * 2048 + kr * 128 + c4 * 4] = ldr[iL];
    }
    __syncthreads();

    u64 a1[4], a2[4];
    #pragma unroll
    for (int p = 0; p < 4; p++) { a1[p] = 0ull; a2[p] = 0ull; }
    for (int ch = 0; ch < NC; ch++) {
        int cur = ch & 1;
        if (ch + 1 < NC) {
            int k0 = (ch + 1) * 16;
            #pragma unroll
            for (int iL = 0; iL < 4; iL++) {
                int idx = t + iL * 256;
                int mat = idx >> 9, rem = idx & 511, kr = rem >> 5, c4 = rem & 31;
                const float* w = mat ? wns : ws;
                ldr[iL] = *(const float4*)(w + (size_t)(k0 + kr) * CS + c0 + c4 * 4);
            }
        }
        #pragma unroll
        for (int kk = 0; kk < 16; kk++) {
            int k = ch * 16 + kk;
            float w1 = wbf[cur * 4096 + kk * 128 + tx];
            float w2 = wbf[cur * 4096 + 2048 + kk * 128 + tx];
            u64 w1p = pk2(w1, w1), w2p = pk2(w2, w2);
            const u64* sp = (const u64*)&st[k * ST20 + ty * 8];
            #pragma unroll
            for (int p = 0; p < 4; p++) {
                a1[p] = ffma2(sp[p], w1p, a1[p]);
                a2[p] = ffma2(sp[p], w2p, a2[p]);
            }
        }
        if (ch + 1 < NC) {
            int nb = (ch + 1) & 1;
            #pragma unroll
            for (int iL = 0; iL < 4; iL++) {
                int idx = t + iL * 256;
                int mat = idx >> 9, rem = idx & 511, kr = rem >> 5, c4 = rem & 31;
                *(float4*)&wbf[nb * 4096 + mat * 2048 + kr * 128 + c4 * 4] = ldr[iL];
            }
        }
        __syncthreads();
    }
    float bsc = bs[c];
    #pragma unroll
    for (int p = 0; p < 4; p++) {
        float x0, x1, y0, y1;
        upk2(a1[p], x0, x1); upk2(a2[p], y0, y1);
        int r0 = i0 + ty * 8 + 2 * p;
        g_a[r0 * CS + c]       = sigm(x0 + bsc) * g_aln[r0 * CS + c]       + y0;
        g_a[(r0 + 1) * CS + c] = sigm(x1 + bsc) * g_aln[(r0 + 1) * CS + c] + y1;
    }
}

// =====================================================================
// Kernel 2: QKV + gate. grid (3,64,4), block 256, static smem ~46 KB.
// =====================================================================
__global__ void __launch_bounds__(256) k_qkvg(const float* __restrict__ wq,
                                              const float* __restrict__ bq,
                                              const float* __restrict__ wk,
                                              const float* __restrict__ wv,
                                              const float* __restrict__ wg) {
    __shared__ __align__(16) float st[CS * ST20];
    __shared__ __align__(16) float wbf[2 * 16 * 128];
    int t  = threadIdx.x;
    int tx = t & 127, ty = t >> 7;
    int m  = blockIdx.z;
    int i0 = blockIdx.y * 16;
    int c0 = blockIdx.x * 128;
    int c  = c0 + tx;
    const float* w = (m == 0) ? wq : (m == 1) ? wk : (m == 2) ? wv : wg;

    for (int r = 0; r < 16; r++)
        for (int kk = t; kk < CS; kk += 256)
            st[kk * ST20 + r] = g_a[(i0 + r) * CS + kk];

    const int NC = CS / 16;
    float4 ldr[2];
    #pragma unroll
    for (int iL = 0; iL < 2; iL++) {
        int idx = t + iL * 256;
        int kr = idx >> 5, c4 = idx & 31;
        ldr[iL] = *(const float4*)(w + (size_t)kr * CS + c0 + c4 * 4);
    }
    #pragma unroll
    for (int iL = 0; iL < 2; iL++) {
        int idx = t + iL * 256;
        int kr = idx >> 5, c4 = idx & 31;
        *(float4*)&wbf[kr * 128 + c4 * 4] = ldr[iL];
    }
    __syncthreads();

    u64 acc[4];
    #pragma unroll
    for (int p = 0; p < 4; p++) acc[p] = 0ull;
    for (int ch = 0; ch < NC; ch++) {
        int cur = ch & 1;
        if (ch + 1 < NC) {
            int k0 = (ch + 1) * 16;
            #pragma unroll
            for (int iL = 0; iL < 2; iL++) {
                int idx = t + iL * 256;
                int kr = idx >> 5, c4 = idx & 31;
                ldr[iL] = *(const float4*)(w + (size_t)(k0 + kr) * CS + c0 + c4 * 4);
            }
        }
        #pragma unroll
        for (int kk = 0; kk < 16; kk++) {
            int k = ch * 16 + kk;
            float wv_ = wbf[cur * 2048 + kk * 128 + tx];
            u64 wp = pk2(wv_, wv_);
            const u64* sp = (const u64*)&st[k * ST20 + ty * 8];
            #pragma unroll
            for (int p = 0; p < 4; p++) acc[p] = ffma2(sp[p], wp, acc[p]);
        }
        if (ch + 1 < NC) {
            int nb = (ch + 1) & 1;
            #pragma unroll
            for (int iL = 0; iL < 2; iL++) {
                int idx = t + iL * 256;
                int kr = idx >> 5, c4 = idx & 31;
                *(float4*)&wbf[nb * 2048 + kr * 128 + c4 * 4] = ldr[iL];
            }
        }
        __syncthreads();
    }
    int h = c / DH, d = c - h * DH;
    float bqc = (m == 0) ? bq[c] : 0.0f;
    #pragma unroll
    for (int p = 0; p < 4; p++) {
        float v0, v1; upk2(acc[p], v0, v1);
        int r0 = i0 + ty * 8 + 2 * p;
        int idx0 = h * (NSEQ * DH) + r0 * DH + d;
        int idx1 = idx0 + DH;
        if (m == 0)      { g_q[idx0] = (v0 + bqc) * RSQRT_D; g_q[idx1] = (v1 + bqc) * RSQRT_D; }
        else if (m == 1) { g_k[idx0] = v0;                   g_k[idx1] = v1; }
        else if (m == 2) { g_v[idx0] = v0;                   g_v[idx1] = v1; }
        else             { g_g[idx0] = sigm(v0);             g_g[idx1] = sigm(v1); }
    }
}

// =====================================================================
// Kernel G: gate = sigmoid(s_i@ws2 + bs2), runs on side stream.
// grid (3,64), block 256.
// =====================================================================
__global__ void __launch_bounds__(256) k_gate(const float* __restrict__ s_i,
                                              const float* __restrict__ ws2,
                                              const float* __restrict__ bs2) {
    __shared__ __align__(16) float st[CS * ST20];
    __shared__ __align__(16) float wbf[2 * 16 * 128];
    int t  = threadIdx.x;
    int tx = t & 127, ty = t >> 7;
    int i0 = blockIdx.y * 16;
    int c0 = blockIdx.x * 128;
    int c  = c0 + tx;

    for (int r = 0; r < 16; r++)
        for (int kk = t; kk < CS; kk += 256)
            st[kk * ST20 + r] = s_i[(i0 + r) * CS + kk];

    const int NC = CS / 16;
    float4 ldr[2];
    #pragma unroll
    for (int iL = 0; iL < 2; iL++) {
        int idx = t + iL * 256;
        int kr = idx >> 5, c4 = idx & 31;
        ldr[iL] = *(const float4*)(ws2 + (size_t)kr * CS + c0 + c4 * 4);
    }
    #pragma unroll
    for (int iL = 0; iL < 2; iL++) {
        int idx = t + iL * 256;
        int kr = idx >> 5, c4 = idx & 31;
        *(float4*)&wbf[kr * 128 + c4 * 4] = ldr[iL];
    }
    __syncthreads();

    u64 acc[4];
    #pragma unroll
    for (int p = 0; p < 4; p++) acc[p] = 0ull;
    for (int ch = 0; ch < NC; ch++) {
        int cur = ch & 1;
        if (ch + 1 < NC) {
            int k0 = (ch + 1) * 16;
            #pragma unroll
            for (int iL = 0; iL < 2; iL++) {
                int idx = t + iL * 256;
                int kr = idx >> 5, c4 = idx & 31;
                ldr[iL] = *(const float4*)(ws2 + (size_t)(k0 + kr) * CS + c0 + c4 * 4);
            }
        }
        #pragma unroll
        for (int kk = 0; kk < 16; kk++) {
            int k = ch * 16 + kk;
            float wv_ = wbf[cur * 2048 + kk * 128 + tx];
            u64 wp = pk2(wv_, wv_);
            const u64* sp = (const u64*)&st[k * ST20 + ty * 8];
            #pragma unroll
            for (int p = 0; p < 4; p++) acc[p] = ffma2(sp[p], wp, acc[p]);
        }
        if (ch + 1 < NC) {
            int nb = (ch + 1) & 1;
            #pragma unroll
            for (int iL = 0; iL < 2; iL++) {
                int idx = t + iL * 256;
                int kr = idx >> 5, c4 = idx & 31;
                *(float4*)&wbf[nb * 2048 + kr * 128 + c4 * 4] = ldr[iL];
            }
        }
        __syncthreads();
    }
    float bsc = bs2[c];
    #pragma unroll
    for (int p = 0; p < 4; p++) {
        float v0, v1; upk2(acc[p], v0, v1);
        int r0 = i0 + ty * 8 + 2 * p;
        g_gate[r0 * CS + c]       = sigm(v0 + bsc);
        g_gate[(r0 + 1) * CS + c] = sigm(v1 + bsc);
    }
}

// =====================================================================
// Kernel 3: pair bias. grid (8,1024), block 128, dyn smem ~74 KB.
// =====================================================================
#define PAIR_SMEM (128*132*4 + NH*64*8 + 2*NH*4)
__global__ void __launch_bounds__(128) k_pair(const float* __restrict__ z) {
    extern __shared__ float sm[];
    float* zs  = sm;
    u64*   wsm = (u64*)(sm + 128 * 132);
    float* WH  = (float*)(wsm + NH * 64);
    float* CH  = WH + NH;
    int t  = threadIdx.x;
    int i  = blockIdx.y;
    int j0 = blockIdx.x * 128;

    #pragma unroll
    for (int p = 0; p < 8; p++) wsm[t + p * 128] = g_wpk[t + p * 128];
    if (t < NH)            WH[t]      = g_WH[t];
    else if (t < 2 * NH)   CH[t - NH] = g_CH[t - NH];

    const float4* zg = (const float4*)(z + (size_t)i * (NSEQ * CZ) + (size_t)j0 * CZ);
    #pragma unroll
    for (int p = 0; p < 32; p++) {
        int f = t + p * 128;
        int jl = f >> 5, c4 = f & 31;
        *(float4*)&zs[jl * 132 + c4 * 4] = zg[(size_t)jl * 32 + c4];
    }
    __syncthreads();

    u64 acc[NH];
    #pragma unroll
    for (int h = 0; h < NH; h++) acc[h] = 0ull;
    u64 s2 = 0ull, q2 = 0ull;
    const float* zr = zs + t * 132;
    #pragma unroll 4
    for (int c4 = 0; c4 < 32; c4++) {
        float4 v = *(const float4*)&zr[c4 * 4];
        u64 v01 = pk2(v.x, v.y), v23 = pk2(v.z, v.w);
        s2 = fadd2(s2, fadd2(v01, v23));
        q2 = ffma2(v01, v01, q2);
        q2 = ffma2(v23, v23, q2);
        const u64* base = wsm + 2 * c4;
        #pragma unroll
        for (int h = 0; h < NH; h++) {
            ulonglong2 wv2 = *(const ulonglong2*)(base + h * 64);
            acc[h] = ffma2(v01, wv2.x, acc[h]);
            acc[h] = ffma2(v23, wv2.y, acc[h]);
        }
    }
    float sa, sb, qa, qb;
    upk2(s2, sa, sb); upk2(q2, qa, qb);
    float mean = (sa + sb) * (1.0f / CZ);
    float var  = (qa + qb) * (1.0f / CZ) - mean * mean;
    float rstd = rsqrtf(var + 1e-5f);
    int j = j0 + t;
    float* bo = g_bias + (size_t)i * NSEQ + j;
    #pragma unroll
    for (int h = 0; h < NH; h++) {
        float x0, x1; upk2(acc[h], x0, x1);
        bo[(size_t)h * NN] = ((x0 + x1) - mean * WH[h]) * rstd + CH[h];
    }
}

// =====================================================================
// Kernel 4: two-pass flash attention, f32x2-packed. grid (64,16),
// block 512, dyn smem 208 KB. K/V as u64 pairs, row stride 13 u64
// (conflict-free per half-warp).
// =====================================================================
#define ATT_SMEM (2 * NSEQ * 13 * 8)
__global__ void __launch_bounds__(512) k_attn() {
    extern __shared__ __align__(16) u64 sm8[];
    u64* ks_ = sm8;
    u64* vs_ = sm8 + NSEQ * 13;
    int h  = blockIdx.y;
    int i0 = blockIdx.x * 16;
    int t  = threadIdx.x;
    const float4* kg4 = (const float4*)(g_k + (size_t)h * NSEQ * DH);
    const float4* vg4 = (const float4*)(g_v + (size_t)h * NSEQ * DH);
    for (int idx = t; idx < NSEQ * 6; idx += 512) {
        int j = idx / 6, q4 = idx - j * 6;
        float4 kv = kg4[idx];
        ks_[j * 13 + 2 * q4]     = pk2(kv.x, kv.y);
        ks_[j * 13 + 2 * q4 + 1] = pk2(kv.z, kv.w);
        float4 vv = vg4[idx];
        vs_[j * 13 + 2 * q4]     = pk2(vv.x, vv.y);
        vs_[j * 13 + 2 * q4 + 1] = pk2(vv.z, vv.w);
    }
    __syncthreads();
    int w = t >> 5, lane = t & 31;
    int i = i0 + w;
    u64 qp[12];
    const float4* qg4 = (const float4*)(g_q + ((size_t)h * NSEQ + i) * DH);
    #pragma unroll
    for (int p = 0; p < 6; p++) {
        float4 qv = qg4[p];
        qp[2 * p]     = pk2(qv.x, qv.y);
        qp[2 * p + 1] = pk2(qv.z, qv.w);
    }
    const float* bp = g_bias + (size_t)h * NN + (size_t)i * NSEQ;

    // pass 1: logits
    float lgs[32];
    float mx = -1e30f;
    #pragma unroll
    for (int s = 0; s < 32; s++) {
        int j = s * 32 + lane;
        const u64* kr = ks_ + j * 13;
        u64 a0 = 0ull, a1 = 0ull;
        #pragma unroll
        for (int p = 0; p < 12; p += 2) {
            a0 = ffma2(qp[p],     kr[p],     a0);
            a1 = ffma2(qp[p + 1], kr[p + 1], a1);
        }
        float x0, x1, y0, y1;
        upk2(a0, x0, x1); upk2(a1, y0, y1);
        float lg = bp[j] + ((x0 + x1) + (y0 + y1));
        lgs[s] = lg;
        mx = fmaxf(mx, lg);
    }
    #pragma unroll
    for (int off = 16; off > 0; off >>= 1)
        mx = fmaxf(mx, __shfl_xor_sync(0xffffffffu, mx, off));

    // pass 2
    float l = 0.0f;
    u64 o2[12];
    #pragma unroll
    for (int p = 0; p < 12; p++) o2[p] = 0ull;
    #pragma unroll
    for (int s = 0; s < 32; s++) {
        float p = __expf(lgs[s] - mx);
        l += p;
        u64 pp = pk2(p, p);
        const u64* vr = vs_ + (s * 32 + lane) * 13;
        #pragma unroll
        for (int q = 0; q < 12; q++) o2[q] = ffma2(pp, vr[q], o2[q]);
    }
    #pragma unroll
    for (int off = 16; off > 0; off >>= 1) l += __shfl_xor_sync(0xffffffffu, l, off);
    float o[DH];
    #pragma unroll
    for (int q = 0; q < 12; q++) upk2(o2[q], o[2 * q], o[2 * q + 1]);
    #pragma unroll
    for (int d = 0; d < DH; d++) {
        #pragma unroll
        for (int off = 16; off > 0; off >>= 1)
            o[d] += __shfl_xor_sync(0xffffffffu, o[d], off);
    }
    if (lane == 0) {
        float inv = 1.0f / l;
        const float* gg = g_g + ((size_t)h * NSEQ + i) * DH;
        float* op = g_o + (size_t)i * HC + h * DH;
        #pragma unroll
        for (int d = 0; d < DH; d++) op[d] = o[d] * inv * gg[d];
    }
}

// =====================================================================
// Kernel 5: out = g_gate * (o@wo). grid (3,64), block 256.
// =====================================================================
__global__ void __launch_bounds__(256) k_out2(const float* __restrict__ wo,
                                              float* __restrict__ out) {
    __shared__ __align__(16) float st[CS * ST20];
    __shared__ __align__(16) float wbf[2 * 16 * 128];
    int t  = threadIdx.x;
    int tx = t & 127, ty = t >> 7;
    int i0 = blockIdx.y * 16;
    int c0 = blockIdx.x * 128;
    int c  = c0 + tx;

    for (int r = 0; r < 16; r++)
        for (int kk = t; kk < CS; kk += 256)
            st[kk * ST20 + r] = g_o[(i0 + r) * CS + kk];

    const int NC = CS / 16;
    float4 ldr[2];
    #pragma unroll
    for (int iL = 0; iL < 2; iL++) {
        int idx = t + iL * 256;
        int kr = idx >> 5, c4 = idx & 31;
        ldr[iL] = *(const float4*)(wo + (size_t)kr * CS + c0 + c4 * 4);
    }
    #pragma unroll
    for (int iL = 0; iL < 2; iL++) {
        int idx = t + iL * 256;
        int kr = idx >> 5, c4 = idx & 31;
        *(float4*)&wbf[kr * 128 + c4 * 4] = ldr[iL];
    }
    __syncthreads();

    u64 acc[4];
    #pragma unroll
    for (int p = 0; p < 4; p++) acc[p] = 0ull;
    for (int ch = 0; ch < NC; ch++) {
        int cur = ch & 1;
        if (ch + 1 < NC) {
            int k0 = (ch + 1) * 16;
            #pragma unroll
            for (int iL = 0; iL < 2; iL++) {
                int idx = t + iL * 256;
                int kr = idx >> 5, c4 = idx & 31;
                ldr[iL] = *(const float4*)(wo + (size_t)(k0 + kr) * CS + c0 + c4 * 4);
            }
        }
        #pragma unroll
        for (int kk = 0; kk < 16; kk++) {
            int k = ch * 16 + kk;
            float wv_ = wbf[cur * 2048 + kk * 128 + tx];
            u64 wp = pk2(wv_, wv_);
            const u64* sp = (const u64*)&st[k * ST20 + ty * 8];
            #pragma unroll
            for (int p = 0; p < 4; p++) acc[p] = ffma2(sp[p], wp, acc[p]);
        }
        if (ch + 1 < NC) {
            int nb = (ch + 1) & 1;
            #pragma unroll
            for (int iL = 0; iL < 2; iL++) {
                int idx = t + iL * 256;
                int kr = idx >> 5, c4 = idx & 31;
                *(float4*)&wbf[nb * 2048 + kr * 128 + c4 * 4] = ldr[iL];
            }
        }
        __syncthreads();
    }
    #pragma unroll
    for (int p = 0; p < 4; p++) {
        float v0, v1; upk2(acc[p], v0, v1);
        int r0 = i0 + ty * 8 + 2 * p;
        out[r0 * CS + c]       = g_gate[r0 * CS + c]       * v0;
        out[(r0 + 1) * CS + c] = g_gate[(r0 + 1) * CS + c] * v1;
    }
}

// =====================================================================
extern "C" void kernel_launch(void* const* d_in, const int* in_sizes, int n_in,
                              void* d_out, int out_size) {
    const float* a_i   = (const float*)d_in[0];
    const float* s_i   = (const float*)d_in[1];
    const float* z     = (const float*)d_in[2];
    const float* lns_w = (const float*)d_in[3];
    const float* aws   = (const float*)d_in[4];
    const float* abs_  = (const float*)d_in[5];
    const float* awns  = (const float*)d_in[6];
    const float* wq    = (const float*)d_in[7];
    const float* bq    = (const float*)d_in[8];
    const float* wk    = (const float*)d_in[9];
    const float* wv    = (const float*)d_in[10];
    const float* lnb_w = (const float*)d_in[11];
    const float* lnb_b = (const float*)d_in[12];
    const float* wb    = (const float*)d_in[13];
    const float* wg    = (const float*)d_in[14];
    const float* wo    = (const float*)d_in[15];
    const float* ws2   = (const float*)d_in[16];
    const float* bs2   = (const float*)d_in[17];
    float* out = (float*)d_out;

    static cudaStream_t sA = 0, sB = 0;
    static cudaEvent_t evF = 0, evA = 0, evB = 0;
    static int inited = 0;
    if (!inited) {
        cudaStreamCreateWithFlags(&sA, cudaStreamNonBlocking);
        cudaStreamCreateWithFlags(&sB, cudaStreamNonBlocking);
        cudaEventCreateWithFlags(&evF, cudaEventDisableTiming);
        cudaEventCreateWithFlags(&evA, cudaEventDisableTiming);
        cudaEventCreateWithFlags(&evB, cudaEventDisableTiming);
        cudaFuncSetAttribute(k_pair,  cudaFuncAttributeMaxDynamicSharedMemorySize, PAIR_SMEM);
        cudaFuncSetAttribute(k_attn,  cudaFuncAttributeMaxDynamicSharedMemorySize, ATT_SMEM);
        cudaFuncSetAttribute(k_adaln, cudaFuncAttributeMaxDynamicSharedMemorySize, ADA_SMEM);
        inited = 1;
    }

    // fork
    cudaEventRecord(evF, 0);
    cudaStreamWaitEvent(sA, evF, 0);
    cudaStreamWaitEvent(sB, evF, 0);

    // stream A: pair-bias path (independent of AdaLN chain)
    k_prep<<<1, 128, 0, sA>>>(lnb_w, lnb_b, wb);
    k_pair<<<dim3(8, NSEQ), 128, PAIR_SMEM, sA>>>(z);

    // stream B: final conditioning gate (depends only on s_i)
    k_gate<<<dim3(3, 64), 256, 0, sB>>>(s_i, ws2, bs2);

    // default stream: AdaLN -> QKV/gate chain
    k_ln<<<NSEQ, CS>>>(a_i, s_i, lns_w);
    k_adaln<<<dim3(3, 64), 256, ADA_SMEM>>>(aws, abs_, awns);
    k_qkvg<<<dim3(3, 64, 4), 256>>>(wq, bq, wk, wv, wg);

    // join
    cudaEventRecord(evA, sA);
    cudaEventRecord(evB, sB);
    cudaStreamWaitEvent(0, evA, 0);
    cudaStreamWaitEvent(0, evB, 0);

    k_attn<<<dim3(64, 16), 512, ATT_SMEM>>>();
    k_out2<<<dim3(3, 64), 256>>>(wo, out);
}

// round 8
// speedup vs baseline: 1.7800x; 1.0824x over previous
#include <cuda_runtime.h>
#include <cuda_bf16.h>
#include <math.h>

#define NSEQ 1024
#define CS   384
#define CZ   128
#define NH   16
#define DH   24
#define HC   384
#define NN   (NSEQ*NSEQ)
#define RSQRT_D 0.2041241452319315f

typedef unsigned long long u64;

__device__ __forceinline__ u64 pk2(float a, float b) {
    u64 r; asm("mov.b64 %0,{%1,%2};" : "=l"(r) : "f"(a), "f"(b)); return r;
}
__device__ __forceinline__ void upk2(u64 v, float& a, float& b) {
    asm("mov.b64 {%0,%1},%2;" : "=f"(a), "=f"(b) : "l"(v));
}
__device__ __forceinline__ u64 ffma2(u64 a, u64 b, u64 c) {
    u64 d; asm("fma.rn.f32x2 %0,%1,%2,%3;" : "=l"(d) : "l"(a), "l"(b), "l"(c)); return d;
}
__device__ __forceinline__ u64 fadd2(u64 a, u64 b) {
    u64 d; asm("add.rn.f32x2 %0,%1,%2;" : "=l"(d) : "l"(a), "l"(b)); return d;
}
__device__ __forceinline__ float sigm(float x) { return 1.0f / (1.0f + __expf(-x)); }

// ------------- scratch (static device globals) -------------
__device__ float g_aln[NSEQ * CS];
__device__ float g_sln[NSEQ * CS];
__device__ float g_a  [NSEQ * CS];
__device__ float g_q  [NH * NSEQ * DH];
__device__ float g_k  [NH * NSEQ * DH];
__device__ float g_v  [NH * NSEQ * DH];
__device__ float g_g  [NH * NSEQ * DH];
__device__ float g_bias[(size_t)NH * NN];   // [h][i][j], 64 MB
__device__ float g_o  [NSEQ * HC];
__device__ float g_gate[NSEQ * CS];         // sigmoid(s_i@ws2+bs2)
__device__ u64   g_wpk[NH * 64];
__device__ float g_WH[NH];
__device__ float g_CH[NH];

// =====================================================================
// Kernel P: one-time prep of pair-bias weights.
// =====================================================================
__global__ void __launch_bounds__(128) k_prep(const float* __restrict__ lnw,
                                              const float* __restrict__ lnb,
                                              const float* __restrict__ wb) {
    int t = threadIdx.x;
    for (int idx = t; idx < NH * 64; idx += 128) {
        int h = idx >> 6, c2 = idx & 63;
        g_wpk[idx] = pk2(lnw[2*c2]     * wb[(2*c2)     * NH + h],
                         lnw[2*c2 + 1] * wb[(2*c2 + 1) * NH + h]);
    }
    if (t < NH) {
        float W = 0, C = 0;
        #pragma unroll 4
        for (int cc = 0; cc < CZ; cc++) {
            float wv = wb[cc * NH + t];
            W += lnw[cc] * wv; C += lnb[cc] * wv;
        }
        g_WH[t] = W; g_CH[t] = C;
    }
}

// =====================================================================
// Kernel 0: row layer norms of a_i and s_i.  grid 1024, block 384.
// =====================================================================
__global__ void __launch_bounds__(384) k_ln(const float* __restrict__ a_i,
                                            const float* __restrict__ s_i,
                                            const float* __restrict__ lnw) {
    __shared__ float red[12][4];
    __shared__ float bcv[4];
    int i = blockIdx.x, t = threadIdx.x;
    float av = a_i[i * CS + t];
    float sv = s_i[i * CS + t];
    float r0 = av, r1 = av * av, r2 = sv, r3 = sv * sv;
    #pragma unroll
    for (int o = 16; o > 0; o >>= 1) {
        r0 += __shfl_down_sync(0xffffffffu, r0, o);
        r1 += __shfl_down_sync(0xffffffffu, r1, o);
        r2 += __shfl_down_sync(0xffffffffu, r2, o);
        r3 += __shfl_down_sync(0xffffffffu, r3, o);
    }
    if ((t & 31) == 0) { int w = t >> 5; red[w][0]=r0; red[w][1]=r1; red[w][2]=r2; red[w][3]=r3; }
    __syncthreads();
    if (t == 0) {
        float s0=0, s1=0, s2=0, s3=0;
        #pragma unroll
        for (int w = 0; w < 12; w++) { s0+=red[w][0]; s1+=red[w][1]; s2+=red[w][2]; s3+=red[w][3]; }
        float ma = s0 * (1.0f/CS), ms = s2 * (1.0f/CS);
        float va = s1 * (1.0f/CS) - ma*ma;
        float vs = s3 * (1.0f/CS) - ms*ms;
        bcv[0]=ma; bcv[1]=rsqrtf(va + 1e-5f);
        bcv[2]=ms; bcv[3]=rsqrtf(vs + 1e-5f);
    }
    __syncthreads();
    g_aln[i*CS + t] = (av - bcv[0]) * bcv[1];
    g_sln[i*CS + t] = (sv - bcv[2]) * bcv[3] * lnw[t];
}

// =====================================================================
// Kernel 1: AdaLN. 16-row x 128-col tiles, block 256, double-buffered
// smem weights. grid (3,64). Dyn smem 62 KB.
// =====================================================================
#define ST20 20
#define ADA_SMEM ((CS*ST20 + 2*2*16*128) * 4)
__global__ void __launch_bounds__(256) k_adaln(const float* __restrict__ ws,
                                               const float* __restrict__ bs,
                                               const float* __restrict__ wns) {
    extern __shared__ float dsm[];
    float* st  = dsm;
    float* wbf = dsm + CS * ST20;
    int t  = threadIdx.x;
    int tx = t & 127, ty = t >> 7;
    int i0 = blockIdx.y * 16;
    int c0 = blockIdx.x * 128;
    int c  = c0 + tx;

    for (int r = 0; r < 16; r++)
        for (int kk = t; kk < CS; kk += 256)
            st[kk * ST20 + r] = g_sln[(i0 + r) * CS + kk];

    const int NC = CS / 16;
    float4 ldr[4];
    #pragma unroll
    for (int iL = 0; iL < 4; iL++) {
        int idx = t + iL * 256;
        int mat = idx >> 9, rem = idx & 511, kr = rem >> 5, c4 = rem & 31;
        const float* w = mat ? wns : ws;
        ldr[iL] = *(const float4*)(w + (size_t)kr * CS + c0 + c4 * 4);
    }
    #pragma unroll
    for (int iL = 0; iL < 4; iL++) {
        int idx = t + iL * 256;
        int mat = idx >> 9, rem = idx & 511, kr = rem >> 5, c4 = rem & 31;
        *(float4*)&wbf[mat * 2048 + kr * 128 + c4 * 4] = ldr[iL];
    }
    __syncthreads();

    u64 a1[4], a2[4];
    #pragma unroll
    for (int p = 0; p < 4; p++) { a1[p] = 0ull; a2[p] = 0ull; }
    for (int ch = 0; ch < NC; ch++) {
        int cur = ch & 1;
        if (ch + 1 < NC) {
            int k0 = (ch + 1) * 16;
            #pragma unroll
            for (int iL = 0; iL < 4; iL++) {
                int idx = t + iL * 256;
                int mat = idx >> 9, rem = idx & 511, kr = rem >> 5, c4 = rem & 31;
                const float* w = mat ? wns : ws;
                ldr[iL] = *(const float4*)(w + (size_t)(k0 + kr) * CS + c0 + c4 * 4);
            }
        }
        #pragma unroll
        for (int kk = 0; kk < 16; kk++) {
            int k = ch * 16 + kk;
            float w1 = wbf[cur * 4096 + kk * 128 + tx];
            float w2 = wbf[cur * 4096 + 2048 + kk * 128 + tx];
            u64 w1p = pk2(w1, w1), w2p = pk2(w2, w2);
            const u64* sp = (const u64*)&st[k * ST20 + ty * 8];
            #pragma unroll
            for (int p = 0; p < 4; p++) {
                a1[p] = ffma2(sp[p], w1p, a1[p]);
                a2[p] = ffma2(sp[p], w2p, a2[p]);
            }
        }
        if (ch + 1 < NC) {
            int nb = (ch + 1) & 1;
            #pragma unroll
            for (int iL = 0; iL < 4; iL++) {
                int idx = t + iL * 256;
                int mat = idx >> 9, rem = idx & 511, kr = rem >> 5, c4 = rem & 31;
                *(float4*)&wbf[nb * 4096 + mat * 2048 + kr * 128 + c4 * 4] = ldr[iL];
            }
        }
        __syncthreads();
    }
    float bsc = bs[c];
    #pragma unroll
    for (int p = 0; p < 4; p++) {
        float x0, x1, y0, y1;
        upk2(a1[p], x0, x1); upk2(a2[p], y0, y1);
        int r0 = i0 + ty * 8 + 2 * p;
        g_a[r0 * CS + c]       = sigm(x0 + bsc) * g_aln[r0 * CS + c]       + y0;
        g_a[(r0 + 1) * CS + c] = sigm(x1 + bsc) * g_aln[(r0 + 1) * CS + c] + y1;
    }
}

// =====================================================================
// Kernel 2: QKV + gate. grid (3,64,4), block 256, static smem ~46 KB.
// =====================================================================
__global__ void __launch_bounds__(256) k_qkvg(const float* __restrict__ wq,
                                              const float* __restrict__ bq,
                                              const float* __restrict__ wk,
                                              const float* __restrict__ wv,
                                              const float* __restrict__ wg) {
    __shared__ __align__(16) float st[CS * ST20];
    __shared__ __align__(16) float wbf[2 * 16 * 128];
    int t  = threadIdx.x;
    int tx = t & 127, ty = t >> 7;
    int m  = blockIdx.z;
    int i0 = blockIdx.y * 16;
    int c0 = blockIdx.x * 128;
    int c  = c0 + tx;
    const float* w = (m == 0) ? wq : (m == 1) ? wk : (m == 2) ? wv : wg;

    for (int r = 0; r < 16; r++)
        for (int kk = t; kk < CS; kk += 256)
            st[kk * ST20 + r] = g_a[(i0 + r) * CS + kk];

    const int NC = CS / 16;
    float4 ldr[2];
    #pragma unroll
    for (int iL = 0; iL < 2; iL++) {
        int idx = t + iL * 256;
        int kr = idx >> 5, c4 = idx & 31;
        ldr[iL] = *(const float4*)(w + (size_t)kr * CS + c0 + c4 * 4);
    }
    #pragma unroll
    for (int iL = 0; iL < 2; iL++) {
        int idx = t + iL * 256;
        int kr = idx >> 5, c4 = idx & 31;
        *(float4*)&wbf[kr * 128 + c4 * 4] = ldr[iL];
    }
    __syncthreads();

    u64 acc[4];
    #pragma unroll
    for (int p = 0; p < 4; p++) acc[p] = 0ull;
    for (int ch = 0; ch < NC; ch++) {
        int cur = ch & 1;
        if (ch + 1 < NC) {
            int k0 = (ch + 1) * 16;
            #pragma unroll
            for (int iL = 0; iL < 2; iL++) {
                int idx = t + iL * 256;
                int kr = idx >> 5, c4 = idx & 31;
                ldr[iL] = *(const float4*)(w + (size_t)(k0 + kr) * CS + c0 + c4 * 4);
            }
        }
        #pragma unroll
        for (int kk = 0; kk < 16; kk++) {
            int k = ch * 16 + kk;
            float wv_ = wbf[cur * 2048 + kk * 128 + tx];
            u64 wp = pk2(wv_, wv_);
            const u64* sp = (const u64*)&st[k * ST20 + ty * 8];
            #pragma unroll
            for (int p = 0; p < 4; p++) acc[p] = ffma2(sp[p], wp, acc[p]);
        }
        if (ch + 1 < NC) {
            int nb = (ch + 1) & 1;
            #pragma unroll
            for (int iL = 0; iL < 2; iL++) {
                int idx = t + iL * 256;
                int kr = idx >> 5, c4 = idx & 31;
                *(float4*)&wbf[nb * 2048 + kr * 128 + c4 * 4] = ldr[iL];
            }
        }
        __syncthreads();
    }
    int h = c / DH, d = c - h * DH;
    float bqc = (m == 0) ? bq[c] : 0.0f;
    #pragma unroll
    for (int p = 0; p < 4; p++) {
        float v0, v1; upk2(acc[p], v0, v1);
        int r0 = i0 + ty * 8 + 2 * p;
        int idx0 = h * (NSEQ * DH) + r0 * DH + d;
        int idx1 = idx0 + DH;
        if (m == 0)      { g_q[idx0] = (v0 + bqc) * RSQRT_D; g_q[idx1] = (v1 + bqc) * RSQRT_D; }
        else if (m == 1) { g_k[idx0] = v0;                   g_k[idx1] = v1; }
        else if (m == 2) { g_v[idx0] = v0;                   g_v[idx1] = v1; }
        else             { g_g[idx0] = sigm(v0);             g_g[idx1] = sigm(v1); }
    }
}

// =====================================================================
// Kernel G: gate = sigmoid(s_i@ws2 + bs2), runs on side stream.
// =====================================================================
__global__ void __launch_bounds__(256) k_gate(const float* __restrict__ s_i,
                                              const float* __restrict__ ws2,
                                              const float* __restrict__ bs2) {
    __shared__ __align__(16) float st[CS * ST20];
    __shared__ __align__(16) float wbf[2 * 16 * 128];
    int t  = threadIdx.x;
    int tx = t & 127, ty = t >> 7;
    int i0 = blockIdx.y * 16;
    int c0 = blockIdx.x * 128;
    int c  = c0 + tx;

    for (int r = 0; r < 16; r++)
        for (int kk = t; kk < CS; kk += 256)
            st[kk * ST20 + r] = s_i[(i0 + r) * CS + kk];

    const int NC = CS / 16;
    float4 ldr[2];
    #pragma unroll
    for (int iL = 0; iL < 2; iL++) {
        int idx = t + iL * 256;
        int kr = idx >> 5, c4 = idx & 31;
        ldr[iL] = *(const float4*)(ws2 + (size_t)kr * CS + c0 + c4 * 4);
    }
    #pragma unroll
    for (int iL = 0; iL < 2; iL++) {
        int idx = t + iL * 256;
        int kr = idx >> 5, c4 = idx & 31;
        *(float4*)&wbf[kr * 128 + c4 * 4] = ldr[iL];
    }
    __syncthreads();

    u64 acc[4];
    #pragma unroll
    for (int p = 0; p < 4; p++) acc[p] = 0ull;
    for (int ch = 0; ch < NC; ch++) {
        int cur = ch & 1;
        if (ch + 1 < NC) {
            int k0 = (ch + 1) * 16;
            #pragma unroll
            for (int iL = 0; iL < 2; iL++) {
                int idx = t + iL * 256;
                int kr = idx >> 5, c4 = idx & 31;
                ldr[iL] = *(const float4*)(ws2 + (size_t)(k0 + kr) * CS + c0 + c4 * 4);
            }
        }
        #pragma unroll
        for (int kk = 0; kk < 16; kk++) {
            int k = ch * 16 + kk;
            float wv_ = wbf[cur * 2048 + kk * 128 + tx];
            u64 wp = pk2(wv_, wv_);
            const u64* sp = (const u64*)&st[k * ST20 + ty * 8];
            #pragma unroll
            for (int p = 0; p < 4; p++) acc[p] = ffma2(sp[p], wp, acc[p]);
        }
        if (ch + 1 < NC) {
            int nb = (ch + 1) & 1;
            #pragma unroll
            for (int iL = 0; iL < 2; iL++) {
                int idx = t + iL * 256;
                int kr = idx >> 5, c4 = idx & 31;
                *(float4*)&wbf[nb * 2048 + kr * 128 + c4 * 4] = ldr[iL];
            }
        }
        __syncthreads();
    }
    float bsc = bs2[c];
    #pragma unroll
    for (int p = 0; p < 4; p++) {
        float v0, v1; upk2(acc[p], v0, v1);
        int r0 = i0 + ty * 8 + 2 * p;
        g_gate[r0 * CS + c]       = sigm(v0 + bsc);
        g_gate[(r0 + 1) * CS + c] = sigm(v1 + bsc);
    }
}

// =====================================================================
// Kernel 3: pair bias. grid (8,1024), block 128, dyn smem ~74 KB.
// =====================================================================
#define PAIR_SMEM (128*132*4 + NH*64*8 + 2*NH*4)
__global__ void __launch_bounds__(128) k_pair(const float* __restrict__ z) {
    extern __shared__ float sm[];
    float* zs  = sm;
    u64*   wsm = (u64*)(sm + 128 * 132);
    float* WH  = (float*)(wsm + NH * 64);
    float* CH  = WH + NH;
    int t  = threadIdx.x;
    int i  = blockIdx.y;
    int j0 = blockIdx.x * 128;

    #pragma unroll
    for (int p = 0; p < 8; p++) wsm[t + p * 128] = g_wpk[t + p * 128];
    if (t < NH)            WH[t]      = g_WH[t];
    else if (t < 2 * NH)   CH[t - NH] = g_CH[t - NH];

    const float4* zg = (const float4*)(z + (size_t)i * (NSEQ * CZ) + (size_t)j0 * CZ);
    #pragma unroll
    for (int p = 0; p < 32; p++) {
        int f = t + p * 128;
        int jl = f >> 5, c4 = f & 31;
        *(float4*)&zs[jl * 132 + c4 * 4] = zg[(size_t)jl * 32 + c4];
    }
    __syncthreads();

    u64 acc[NH];
    #pragma unroll
    for (int h = 0; h < NH; h++) acc[h] = 0ull;
    u64 s2 = 0ull, q2 = 0ull;
    const float* zr = zs + t * 132;
    #pragma unroll 4
    for (int c4 = 0; c4 < 32; c4++) {
        float4 v = *(const float4*)&zr[c4 * 4];
        u64 v01 = pk2(v.x, v.y), v23 = pk2(v.z, v.w);
        s2 = fadd2(s2, fadd2(v01, v23));
        q2 = ffma2(v01, v01, q2);
        q2 = ffma2(v23, v23, q2);
        const u64* base = wsm + 2 * c4;
        #pragma unroll
        for (int h = 0; h < NH; h++) {
            ulonglong2 wv2 = *(const ulonglong2*)(base + h * 64);
            acc[h] = ffma2(v01, wv2.x, acc[h]);
            acc[h] = ffma2(v23, wv2.y, acc[h]);
        }
    }
    float sa, sb, qa, qb;
    upk2(s2, sa, sb); upk2(q2, qa, qb);
    float mean = (sa + sb) * (1.0f / CZ);
    float var  = (qa + qb) * (1.0f / CZ) - mean * mean;
    float rstd = rsqrtf(var + 1e-5f);
    int j = j0 + t;
    float* bo = g_bias + (size_t)i * NSEQ + j;
    #pragma unroll
    for (int h = 0; h < NH; h++) {
        float x0, x1; upk2(acc[h], x0, x1);
        bo[(size_t)h * NN] = ((x0 + x1) - mean * WH[h]) * rstd + CH[h];
    }
}

// =====================================================================
// Kernel 4: two-pass flash attention, 2 query-rows per warp.
// grid (64,16), block 256 (8 warps -> 16 i-rows), dyn smem 208 KB.
// Each K/V smem row read serves TWO logit/PV chains; 248-reg budget
// at 256 thr keeps lgsA/lgsB in registers (no spills).
// =====================================================================
#define ATT_SMEM (2 * NSEQ * 13 * 8)
__global__ void __launch_bounds__(256) k_attn() {
    extern __shared__ __align__(16) u64 sm8[];
    u64* ks_ = sm8;
    u64* vs_ = sm8 + NSEQ * 13;
    int h  = blockIdx.y;
    int i0 = blockIdx.x * 16;
    int t  = threadIdx.x;
    const float4* kg4 = (const float4*)(g_k + (size_t)h * NSEQ * DH);
    const float4* vg4 = (const float4*)(g_v + (size_t)h * NSEQ * DH);
    for (int idx = t; idx < NSEQ * 6; idx += 256) {
        int j = idx / 6, q4 = idx - j * 6;
        float4 kv = kg4[idx];
        ks_[j * 13 + 2 * q4]     = pk2(kv.x, kv.y);
        ks_[j * 13 + 2 * q4 + 1] = pk2(kv.z, kv.w);
        float4 vv = vg4[idx];
        vs_[j * 13 + 2 * q4]     = pk2(vv.x, vv.y);
        vs_[j * 13 + 2 * q4 + 1] = pk2(vv.z, vv.w);
    }
    __syncthreads();
    int w = t >> 5, lane = t & 31;
    int iA = i0 + 2 * w, iB = iA + 1;

    u64 qpA[12], qpB[12];
    {
        const float4* qgA = (const float4*)(g_q + ((size_t)h * NSEQ + iA) * DH);
        const float4* qgB = (const float4*)(g_q + ((size_t)h * NSEQ + iB) * DH);
        #pragma unroll
        for (int p = 0; p < 6; p++) {
            float4 qa = qgA[p];
            qpA[2 * p]     = pk2(qa.x, qa.y);
            qpA[2 * p + 1] = pk2(qa.z, qa.w);
            float4 qb = qgB[p];
            qpB[2 * p]     = pk2(qb.x, qb.y);
            qpB[2 * p + 1] = pk2(qb.z, qb.w);
        }
    }
    const float* bpA = g_bias + (size_t)h * NN + (size_t)iA * NSEQ;
    const float* bpB = bpA + NSEQ;

    // ---- pass 1: logits for both rows, shared K reads ----
    float lgsA[32], lgsB[32];
    float mxA = -1e30f, mxB = -1e30f;
    #pragma unroll
    for (int s = 0; s < 32; s++) {
        int j = s * 32 + lane;
        const u64* kr = ks_ + j * 13;
        u64 a0 = 0ull, a1 = 0ull, b0 = 0ull, b1 = 0ull;
        #pragma unroll
        for (int p = 0; p < 12; p += 2) {
            u64 k0 = kr[p], k1 = kr[p + 1];
            a0 = ffma2(qpA[p],     k0, a0);
            a1 = ffma2(qpA[p + 1], k1, a1);
            b0 = ffma2(qpB[p],     k0, b0);
            b1 = ffma2(qpB[p + 1], k1, b1);
        }
        float x0, x1, y0, y1;
        upk2(a0, x0, x1); upk2(a1, y0, y1);
        float lgA = bpA[j] + ((x0 + x1) + (y0 + y1));
        upk2(b0, x0, x1); upk2(b1, y0, y1);
        float lgB = bpB[j] + ((x0 + x1) + (y0 + y1));
        lgsA[s] = lgA; mxA = fmaxf(mxA, lgA);
        lgsB[s] = lgB; mxB = fmaxf(mxB, lgB);
    }
    #pragma unroll
    for (int off = 16; off > 0; off >>= 1) {
        mxA = fmaxf(mxA, __shfl_xor_sync(0xffffffffu, mxA, off));
        mxB = fmaxf(mxB, __shfl_xor_sync(0xffffffffu, mxB, off));
    }

    // ---- pass 2: exp + PV for both rows, shared V reads ----
    float lA = 0.0f, lB = 0.0f;
    u64 oA[12], oB[12];
    #pragma unroll
    for (int p = 0; p < 12; p++) { oA[p] = 0ull; oB[p] = 0ull; }
    #pragma unroll
    for (int s = 0; s < 32; s++) {
        float pA = __expf(lgsA[s] - mxA);
        float pB = __expf(lgsB[s] - mxB);
        lA += pA; lB += pB;
        u64 ppA = pk2(pA, pA), ppB = pk2(pB, pB);
        const u64* vr = vs_ + (s * 32 + lane) * 13;
        #pragma unroll
        for (int q = 0; q < 12; q++) {
            u64 vv = vr[q];
            oA[q] = ffma2(ppA, vv, oA[q]);
            oB[q] = ffma2(ppB, vv, oB[q]);
        }
    }
    #pragma unroll
    for (int off = 16; off > 0; off >>= 1) {
        lA += __shfl_xor_sync(0xffffffffu, lA, off);
        lB += __shfl_xor_sync(0xffffffffu, lB, off);
    }
    float fA[DH], fB[DH];
    #pragma unroll
    for (int q = 0; q < 12; q++) {
        upk2(oA[q], fA[2 * q], fA[2 * q + 1]);
        upk2(oB[q], fB[2 * q], fB[2 * q + 1]);
    }
    #pragma unroll
    for (int d = 0; d < DH; d++) {
        #pragma unroll
        for (int off = 16; off > 0; off >>= 1) {
            fA[d] += __shfl_xor_sync(0xffffffffu, fA[d], off);
            fB[d] += __shfl_xor_sync(0xffffffffu, fB[d], off);
        }
    }
    if (lane == 0) {
        float invA = 1.0f / lA;
        const float* ggA = g_g + ((size_t)h * NSEQ + iA) * DH;
        float* opA = g_o + (size_t)iA * HC + h * DH;
        #pragma unroll
        for (int d = 0; d < DH; d++) opA[d] = fA[d] * invA * ggA[d];
        float invB = 1.0f / lB;
        const float* ggB = g_g + ((size_t)h * NSEQ + iB) * DH;
        float* opB = g_o + (size_t)iB * HC + h * DH;
        #pragma unroll
        for (int d = 0; d < DH; d++) opB[d] = fB[d] * invB * ggB[d];
    }
}

// =====================================================================
// Kernel 5: out = g_gate * (o@wo). grid (3,64), block 256.
// =====================================================================
__global__ void __launch_bounds__(256) k_out2(const float* __restrict__ wo,
                                              float* __restrict__ out) {
    __shared__ __align__(16) float st[CS * ST20];
    __shared__ __align__(16) float wbf[2 * 16 * 128];
    int t  = threadIdx.x;
    int tx = t & 127, ty = t >> 7;
    int i0 = blockIdx.y * 16;
    int c0 = blockIdx.x * 128;
    int c  = c0 + tx;

    for (int r = 0; r < 16; r++)
        for (int kk = t; kk < CS; kk += 256)
            st[kk * ST20 + r] = g_o[(i0 + r) * CS + kk];

    const int NC = CS / 16;
    float4 ldr[2];
    #pragma unroll
    for (int iL = 0; iL < 2; iL++) {
        int idx = t + iL * 256;
        int kr = idx >> 5, c4 = idx & 31;
        ldr[iL] = *(const float4*)(wo + (size_t)kr * CS + c0 + c4 * 4);
    }
    #pragma unroll
    for (int iL = 0; iL < 2; iL++) {
        int idx = t + iL * 256;
        int kr = idx >> 5, c4 = idx & 31;
        *(float4*)&wbf[kr * 128 + c4 * 4] = ldr[iL];
    }
    __syncthreads();

    u64 acc[4];
    #pragma unroll
    for (int p = 0; p < 4; p++) acc[p] = 0ull;
    for (int ch = 0; ch < NC; ch++) {
        int cur = ch & 1;
        if (ch + 1 < NC) {
            int k0 = (ch + 1) * 16;
            #pragma unroll
            for (int iL = 0; iL < 2; iL++) {
                int idx = t + iL * 256;
                int kr = idx >> 5, c4 = idx & 31;
                ldr[iL] = *(const float4*)(wo + (size_t)(k0 + kr) * CS + c0 + c4 * 4);
            }
        }
        #pragma unroll
        for (int kk = 0; kk < 16; kk++) {
            int k = ch * 16 + kk;
            float wv_ = wbf[cur * 2048 + kk * 128 + tx];
            u64 wp = pk2(wv_, wv_);
            const u64* sp = (const u64*)&st[k * ST20 + ty * 8];
            #pragma unroll
            for (int p = 0; p < 4; p++) acc[p] = ffma2(sp[p], wp, acc[p]);
        }
        if (ch + 1 < NC) {
            int nb = (ch + 1) & 1;
            #pragma unroll
            for (int iL = 0; iL < 2; iL++) {
                int idx = t + iL * 256;
                int kr = idx >> 5, c4 = idx & 31;
                *(float4*)&wbf[nb * 2048 + kr * 128 + c4 * 4] = ldr[iL];
            }
        }
        __syncthreads();
    }
    #pragma unroll
    for (int p = 0; p < 4; p++) {
        float v0, v1; upk2(acc[p], v0, v1);
        int r0 = i0 + ty * 8 + 2 * p;
        out[r0 * CS + c]       = g_gate[r0 * CS + c]       * v0;
        out[(r0 + 1) * CS + c] = g_gate[(r0 + 1) * CS + c] * v1;
    }
}

// =====================================================================
extern "C" void kernel_launch(void* const* d_in, const int* in_sizes, int n_in,
                              void* d_out, int out_size) {
    const float* a_i   = (const float*)d_in[0];
    const float* s_i   = (const float*)d_in[1];
    const float* z     = (const float*)d_in[2];
    const float* lns_w = (const float*)d_in[3];
    const float* aws   = (const float*)d_in[4];
    const float* abs_  = (const float*)d_in[5];
    const float* awns  = (const float*)d_in[6];
    const float* wq    = (const float*)d_in[7];
    const float* bq    = (const float*)d_in[8];
    const float* wk    = (const float*)d_in[9];
    const float* wv    = (const float*)d_in[10];
    const float* lnb_w = (const float*)d_in[11];
    const float* lnb_b = (const float*)d_in[12];
    const float* wb    = (const float*)d_in[13];
    const float* wg    = (const float*)d_in[14];
    const float* wo    = (const float*)d_in[15];
    const float* ws2   = (const float*)d_in[16];
    const float* bs2   = (const float*)d_in[17];
    float* out = (float*)d_out;

    static cudaStream_t sA = 0, sB = 0;
    static cudaEvent_t evF = 0, evA = 0, evB = 0;
    static int inited = 0;
    if (!inited) {
        cudaStreamCreateWithFlags(&sA, cudaStreamNonBlocking);
        cudaStreamCreateWithFlags(&sB, cudaStreamNonBlocking);
        cudaEventCreateWithFlags(&evF, cudaEventDisableTiming);
        cudaEventCreateWithFlags(&evA, cudaEventDisableTiming);
        cudaEventCreateWithFlags(&evB, cudaEventDisableTiming);
        cudaFuncSetAttribute(k_pair,  cudaFuncAttributeMaxDynamicSharedMemorySize, PAIR_SMEM);
        cudaFuncSetAttribute(k_attn,  cudaFuncAttributeMaxDynamicSharedMemorySize, ATT_SMEM);
        cudaFuncSetAttribute(k_adaln, cudaFuncAttributeMaxDynamicSharedMemorySize, ADA_SMEM);
        inited = 1;
    }

    // fork
    cudaEventRecord(evF, 0);
    cudaStreamWaitEvent(sA, evF, 0);
    cudaStreamWaitEvent(sB, evF, 0);

    // stream A: pair-bias path
    k_prep<<<1, 128, 0, sA>>>(lnb_w, lnb_b, wb);
    k_pair<<<dim3(8, NSEQ), 128, PAIR_SMEM, sA>>>(z);

    // stream B: final conditioning gate
    k_gate<<<dim3(3, 64), 256, 0, sB>>>(s_i, ws2, bs2);

    // default stream: AdaLN -> QKV/gate chain
    k_ln<<<NSEQ, CS>>>(a_i, s_i, lns_w);
    k_adaln<<<dim3(3, 64), 256, ADA_SMEM>>>(aws, abs_, awns);
    k_qkvg<<<dim3(3, 64, 4), 256>>>(wq, bq, wk, wv, wg);

    // join
    cudaEventRecord(evA, sA);
    cudaEventRecord(evB, sB);
    cudaStreamWaitEvent(0, evA, 0);
    cudaStreamWaitEvent(0, evB, 0);

    k_attn<<<dim3(64, 16), 256, ATT_SMEM>>>();
    k_out2<<<dim3(3, 64), 256>>>(wo, out);
}